// round 1
// baseline (speedup 1.0000x reference)
#include <cuda_runtime.h>
#include <math.h>

// Problem constants: B=64, T=1024, D=512, H=512
#define NEGV (-1e30f)

// Scratch (allocation-free rule: __device__ globals)
__device__ float g_K[64 * 1024 * 512];   // 128 MB
__device__ float g_Q[64 * 1024 * 512];   // 128 MB
__device__ float g_V[64 * 1024 * 512];   // 128 MB
__device__ float g_S[67108864];          // 268 MB  (B*T*T logits / probs)

// ---------------------------------------------------------------------------
// Generic NN GEMM: C[m,n] = sum_k A[m,k] * Bm[k,n] (+ bias[n])
// Tiles: 128x128, BK=16, 256 threads, 8x8 per thread. Batched via blockIdx.z.
// ---------------------------------------------------------------------------
__global__ __launch_bounds__(256) void gemm_nn_kernel(
    const float* __restrict__ A, int lda, long long sA,
    const float* __restrict__ Bm, int ldb, long long sB,
    float* __restrict__ C, int ldc, long long sC,
    const float* __restrict__ bias, int Kdim)
{
    A  += (long long)blockIdx.z * sA;
    Bm += (long long)blockIdx.z * sB;
    C  += (long long)blockIdx.z * sC;

    const int mBase = blockIdx.y * 128;
    const int nBase = blockIdx.x * 128;

    __shared__ __align__(16) float As[16][128];
    __shared__ __align__(16) float Bs[16][128];

    const int tid = threadIdx.x;
    const int tn = tid & 15;    // 0..15 -> n micro
    const int tm = tid >> 4;    // 0..15 -> m micro

    float acc[8][8];
#pragma unroll
    for (int i = 0; i < 8; i++)
#pragma unroll
        for (int j = 0; j < 8; j++) acc[i][j] = 0.0f;

    for (int k0 = 0; k0 < Kdim; k0 += 16) {
        // Load A tile 128(m) x 16(k), transpose into As[k][m]
#pragma unroll
        for (int i = 0; i < 2; i++) {
            int idx = tid * 2 + i;          // 0..511 float4 slots
            int row = idx >> 2;             // 0..127
            int kq  = (idx & 3) << 2;       // 0,4,8,12
            float4 v = *(const float4*)(A + (long long)(mBase + row) * lda + k0 + kq);
            As[kq + 0][row] = v.x;
            As[kq + 1][row] = v.y;
            As[kq + 2][row] = v.z;
            As[kq + 3][row] = v.w;
        }
        // Load B tile 16(k) x 128(n) directly
#pragma unroll
        for (int i = 0; i < 2; i++) {
            int idx = tid * 2 + i;
            int kr  = idx >> 5;             // 0..15
            int nq  = (idx & 31) << 2;      // 0..124
            *(float4*)&Bs[kr][nq] =
                *(const float4*)(Bm + (long long)(k0 + kr) * ldb + nBase + nq);
        }
        __syncthreads();

#pragma unroll
        for (int k = 0; k < 16; k++) {
            float a[8], bb[8];
            *(float4*)&a[0]  = *(const float4*)&As[k][tm * 8];
            *(float4*)&a[4]  = *(const float4*)&As[k][tm * 8 + 4];
            *(float4*)&bb[0] = *(const float4*)&Bs[k][tn * 8];
            *(float4*)&bb[4] = *(const float4*)&Bs[k][tn * 8 + 4];
#pragma unroll
            for (int i = 0; i < 8; i++)
#pragma unroll
                for (int j = 0; j < 8; j++)
                    acc[i][j] = fmaf(a[i], bb[j], acc[i][j]);
        }
        __syncthreads();
    }

#pragma unroll
    for (int i = 0; i < 8; i++) {
        long long m = mBase + tm * 8 + i;
#pragma unroll
        for (int j = 0; j < 8; j += 4) {
            int n = nBase + tn * 8 + j;
            float4 o;
            if (bias) {
                o.x = acc[i][j + 0] + bias[n + 0];
                o.y = acc[i][j + 1] + bias[n + 1];
                o.z = acc[i][j + 2] + bias[n + 2];
                o.w = acc[i][j + 3] + bias[n + 3];
            } else {
                o.x = acc[i][j + 0];
                o.y = acc[i][j + 1];
                o.z = acc[i][j + 2];
                o.w = acc[i][j + 3];
            }
            *(float4*)(C + m * ldc + n) = o;
        }
    }
}

// ---------------------------------------------------------------------------
// Scores (NT GEMM): S[b,t,s] = (Q[b,t,:] . K[b,s,:]) / sqrt(512)
// Fused epilogue: sp = dag[s,t] * val; logit = (sp == 0) ? -1e30 : sp
// ---------------------------------------------------------------------------
__global__ __launch_bounds__(256) void scores_kernel(
    const float* __restrict__ Q, const float* __restrict__ Kt,
    const float* __restrict__ dag, float* __restrict__ S)
{
    const long long b = blockIdx.z;
    const float* Qb = Q + b * (1024LL * 512);
    const float* Kb = Kt + b * (1024LL * 512);
    float* Sb = S + b * (1024LL * 1024);

    const int tBase = blockIdx.y * 128;   // query rows t
    const int sBase = blockIdx.x * 128;   // key rows s

    __shared__ __align__(16) float Qs[16][128];
    __shared__ __align__(16) float Ks[16][128];

    const int tid = threadIdx.x;
    const int tn = tid & 15;
    const int tm = tid >> 4;

    float acc[8][8];
#pragma unroll
    for (int i = 0; i < 8; i++)
#pragma unroll
        for (int j = 0; j < 8; j++) acc[i][j] = 0.0f;

    for (int k0 = 0; k0 < 512; k0 += 16) {
#pragma unroll
        for (int i = 0; i < 2; i++) {
            int idx = tid * 2 + i;
            int row = idx >> 2;
            int kq  = (idx & 3) << 2;
            float4 v = *(const float4*)(Qb + (long long)(tBase + row) * 512 + k0 + kq);
            Qs[kq + 0][row] = v.x;
            Qs[kq + 1][row] = v.y;
            Qs[kq + 2][row] = v.z;
            Qs[kq + 3][row] = v.w;
            float4 w = *(const float4*)(Kb + (long long)(sBase + row) * 512 + k0 + kq);
            Ks[kq + 0][row] = w.x;
            Ks[kq + 1][row] = w.y;
            Ks[kq + 2][row] = w.z;
            Ks[kq + 3][row] = w.w;
        }
        __syncthreads();

#pragma unroll
        for (int k = 0; k < 16; k++) {
            float a[8], bb[8];
            *(float4*)&a[0]  = *(const float4*)&Qs[k][tm * 8];
            *(float4*)&a[4]  = *(const float4*)&Qs[k][tm * 8 + 4];
            *(float4*)&bb[0] = *(const float4*)&Ks[k][tn * 8];
            *(float4*)&bb[4] = *(const float4*)&Ks[k][tn * 8 + 4];
#pragma unroll
            for (int i = 0; i < 8; i++)
#pragma unroll
                for (int j = 0; j < 8; j++)
                    acc[i][j] = fmaf(a[i], bb[j], acc[i][j]);
        }
        __syncthreads();
    }

    const float scale = 0.044194173824159216f;  // 1/sqrt(512)
#pragma unroll
    for (int i = 0; i < 8; i++) {
        int t = tBase + tm * 8 + i;
        float ov[8];
#pragma unroll
        for (int j = 0; j < 8; j++) {
            int s = sBase + tn * 8 + j;
            float val = acc[i][j] * scale;
            float sp  = dag[(long long)s * 1024 + t] * val;   // dag.T[t,s]
            ov[j] = (sp == 0.0f) ? NEGV : sp;
        }
        float* dst = Sb + (long long)t * 1024 + sBase + tn * 8;
        *(float4*)(dst + 0) = make_float4(ov[0], ov[1], ov[2], ov[3]);
        *(float4*)(dst + 4) = make_float4(ov[4], ov[5], ov[6], ov[7]);
    }
}

// ---------------------------------------------------------------------------
// Row softmax over 1024 logits; dead rows (all masked) -> 0. In-place on g_S.
// One block of 256 threads per row, 4 elements (1 float4) per thread.
// ---------------------------------------------------------------------------
__global__ __launch_bounds__(256) void softmax_kernel(float* __restrict__ S)
{
    float* p = S + (long long)blockIdx.x * 1024;
    const int tid = threadIdx.x;

    float4 v = *((const float4*)p + tid);

    __shared__ float red[256];
    float m = fmaxf(fmaxf(v.x, v.y), fmaxf(v.z, v.w));
    red[tid] = m;
    __syncthreads();
#pragma unroll
    for (int s = 128; s > 0; s >>= 1) {
        if (tid < s) red[tid] = fmaxf(red[tid], red[tid + s]);
        __syncthreads();
    }
    const float mx = red[0];
    __syncthreads();

    float4 e;
    e.x = __expf(v.x - mx);
    e.y = __expf(v.y - mx);
    e.z = __expf(v.z - mx);
    e.w = __expf(v.w - mx);

    red[tid] = e.x + e.y + e.z + e.w;
    __syncthreads();
#pragma unroll
    for (int s = 128; s > 0; s >>= 1) {
        if (tid < s) red[tid] += red[tid + s];
        __syncthreads();
    }
    const float inv = 1.0f / red[0];

    if (mx < -1e29f) {            // fully masked row -> zeros
        e.x = e.y = e.z = e.w = 0.0f;
    } else {
        e.x *= inv; e.y *= inv; e.z *= inv; e.w *= inv;
    }
    *((float4*)p + tid) = e;
}

// ---------------------------------------------------------------------------
// kernel_launch
// Inputs (metadata order): X, Y, dag, Wk, bk, Wq, bq, Wv, bv
// ---------------------------------------------------------------------------
extern "C" void kernel_launch(void* const* d_in, const int* in_sizes, int n_in,
                              void* d_out, int out_size)
{
    const float* X   = (const float*)d_in[0];
    const float* Y   = (const float*)d_in[1];
    const float* dag = (const float*)d_in[2];
    const float* Wk  = (const float*)d_in[3];
    const float* bk  = (const float*)d_in[4];
    const float* Wq  = (const float*)d_in[5];
    const float* bq  = (const float*)d_in[6];
    const float* Wv  = (const float*)d_in[7];
    const float* bv  = (const float*)d_in[8];
    float* O = (float*)d_out;

    float *Kp, *Qp, *Vp, *Sp;
    cudaGetSymbolAddress((void**)&Kp, g_K);
    cudaGetSymbolAddress((void**)&Qp, g_Q);
    cudaGetSymbolAddress((void**)&Vp, g_V);
    cudaGetSymbolAddress((void**)&Sp, g_S);

    dim3 blk(256);

    // Projections: [65536, 512] @ [512, 512] + bias  (M tiles = 512, N tiles = 4)
    dim3 gproj(4, 512, 1);
    gemm_nn_kernel<<<gproj, blk>>>(X, 512, 0LL, Wk, 512, 0LL, Kp, 512, 0LL, bk, 512);
    gemm_nn_kernel<<<gproj, blk>>>(Y, 512, 0LL, Wq, 512, 0LL, Qp, 512, 0LL, bq, 512);
    gemm_nn_kernel<<<gproj, blk>>>(X, 512, 0LL, Wv, 512, 0LL, Vp, 512, 0LL, bv, 512);

    // Scores + mask: per batch [1024,512] @ [512,1024]^T -> logits in g_S
    dim3 gsc(8, 8, 64);
    scores_kernel<<<gsc, blk>>>(Qp, Kp, dag, Sp);

    // Softmax over each of B*T = 65536 rows
    softmax_kernel<<<65536, blk>>>(Sp);

    // Output: per batch [1024,1024] @ [1024,512] -> d_out
    dim3 gout(4, 8, 64);
    gemm_nn_kernel<<<gout, blk>>>(Sp, 1024, 1024LL * 1024, Vp, 512, 1024LL * 512,
                                  O, 512, 1024LL * 512, (const float*)nullptr, 1024);
}

// round 3
// speedup vs baseline: 2.4127x; 2.4127x over previous
#include <cuda_runtime.h>
#include <cuda_bf16.h>
#include <cstdint>

#define NEGV (-1e30f)

// ============================ scratch (no allocs) ============================
__device__ __nv_bfloat16 g_Xh[33554432], g_Xl[33554432];
__device__ __nv_bfloat16 g_Yh[33554432], g_Yl[33554432];
__device__ __nv_bfloat16 g_Kh[33554432], g_Kl[33554432];
__device__ __nv_bfloat16 g_Qh[33554432], g_Ql[33554432];
__device__ __nv_bfloat16 g_Vth[33554432], g_Vtl[33554432];   // V transposed [b][h][t]
__device__ float         g_S [67108864];                     // logits [b][t][s]
__device__ __nv_bfloat16 g_Ph[67108864], g_Pl[67108864];     // probs hi/lo
__device__ __nv_bfloat16 g_Wth[786432], g_Wtl[786432];       // 3x W^T [h][d]
__device__ float         g_dagT[1048576];                    // dag transposed [t][s]

// ============================ PTX helpers (base sm_103 ISA only) =============
__device__ __forceinline__ uint32_t smem_u32(const void* p) {
    uint32_t a;
    asm("{ .reg .u64 t; cvta.to.shared.u64 t, %1; cvt.u32.u64 %0, t; }" : "=r"(a) : "l"(p));
    return a;
}
#define CP_ASYNC16(dst, src) \
    asm volatile("cp.async.cg.shared.global [%0], [%1], 16;" :: "r"(dst), "l"(src))
#define CP_COMMIT() asm volatile("cp.async.commit_group;" ::: "memory")
#define CP_WAIT(n)  asm volatile("cp.async.wait_group %0;" :: "n"(n) : "memory")

__device__ __forceinline__ void ldsm_x4(uint32_t& r0, uint32_t& r1, uint32_t& r2, uint32_t& r3,
                                        uint32_t addr) {
    asm volatile("ldmatrix.sync.aligned.m8n8.x4.shared.b16 {%0,%1,%2,%3}, [%4];"
                 : "=r"(r0), "=r"(r1), "=r"(r2), "=r"(r3) : "r"(addr));
}
__device__ __forceinline__ void mma_bf16(float* c, const uint32_t* a, uint32_t b0, uint32_t b1) {
    asm volatile(
        "mma.sync.aligned.m16n8k16.row.col.f32.bf16.bf16.f32 "
        "{%0,%1,%2,%3}, {%4,%5,%6,%7}, {%8,%9}, {%0,%1,%2,%3};"
        : "+f"(c[0]), "+f"(c[1]), "+f"(c[2]), "+f"(c[3])
        : "r"(a[0]), "r"(a[1]), "r"(a[2]), "r"(a[3]), "r"(b0), "r"(b1));
}
#define SWZ128(o) ((o) ^ (((o) >> 3) & 0x70))

// ============================ small utility kernels ==========================
__device__ __forceinline__ uint32_t splitpack(float x) {
    __nv_bfloat16 h = __float2bfloat16(x);
    float r = x - __bfloat162float(h);
    __nv_bfloat16 l = __float2bfloat16(r);
    return ((uint32_t)__bfloat16_as_ushort(l) << 16) | (uint32_t)__bfloat16_as_ushort(h);
}

__global__ __launch_bounds__(256) void split_kernel(const float4* __restrict__ src,
                                                    uint2* __restrict__ h, uint2* __restrict__ l) {
    int i = blockIdx.x * 256 + threadIdx.x;
    float4 v = src[i];
    uint32_t p0 = splitpack(v.x), p1 = splitpack(v.y), p2 = splitpack(v.z), p3 = splitpack(v.w);
    uint2 hh, ll;
    hh.x = (p0 & 0xFFFF) | (p1 << 16);  hh.y = (p2 & 0xFFFF) | (p3 << 16);
    ll.x = (p0 >> 16) | (p1 & 0xFFFF0000u);  ll.y = (p2 >> 16) | (p3 & 0xFFFF0000u);
    h[i] = hh; l[i] = ll;
}

__global__ __launch_bounds__(256) void wt_split_kernel(const float* __restrict__ W,
                                                       __nv_bfloat16* __restrict__ th,
                                                       __nv_bfloat16* __restrict__ tl) {
    int i = blockIdx.x * 256 + threadIdx.x;           // Wt[h][d] = W[d][h]
    int hh = i >> 9, d = i & 511;
    float x = W[d * 512 + hh];
    uint32_t p = splitpack(x);
    th[i] = __ushort_as_bfloat16((unsigned short)(p & 0xFFFF));
    tl[i] = __ushort_as_bfloat16((unsigned short)(p >> 16));
}

__global__ __launch_bounds__(256) void dagt_kernel(const float* __restrict__ dag,
                                                   float* __restrict__ dagT) {
    int i = blockIdx.x * 256 + threadIdx.x;           // dagT[t][s] = dag[s][t]
    int t = i >> 10, s = i & 1023;
    dagT[i] = dag[s * 1024 + t];
}

__global__ __launch_bounds__(256) void softmax_kernel(const float* __restrict__ S,
                                                      uint2* __restrict__ Ph, uint2* __restrict__ Pl) {
    const long long row = blockIdx.x;
    const float* p = S + row * 1024;
    const int tid = threadIdx.x;
    float4 v = ((const float4*)p)[tid];

    __shared__ float red[256];
    float m = fmaxf(fmaxf(v.x, v.y), fmaxf(v.z, v.w));
    red[tid] = m; __syncthreads();
#pragma unroll
    for (int s = 128; s > 0; s >>= 1) { if (tid < s) red[tid] = fmaxf(red[tid], red[tid + s]); __syncthreads(); }
    const float mx = red[0]; __syncthreads();

    float4 e;
    e.x = __expf(v.x - mx); e.y = __expf(v.y - mx); e.z = __expf(v.z - mx); e.w = __expf(v.w - mx);
    red[tid] = e.x + e.y + e.z + e.w; __syncthreads();
#pragma unroll
    for (int s = 128; s > 0; s >>= 1) { if (tid < s) red[tid] += red[tid + s]; __syncthreads(); }
    const float inv = 1.0f / red[0];

    if (mx < -1e29f) { e.x = e.y = e.z = e.w = 0.0f; }
    else { e.x *= inv; e.y *= inv; e.z *= inv; e.w *= inv; }

    uint32_t p0 = splitpack(e.x), p1 = splitpack(e.y), p2 = splitpack(e.z), p3 = splitpack(e.w);
    uint2 hh, ll;
    hh.x = (p0 & 0xFFFF) | (p1 << 16);  hh.y = (p2 & 0xFFFF) | (p3 << 16);
    ll.x = (p0 >> 16) | (p1 & 0xFFFF0000u);  ll.y = (p2 >> 16) | (p3 & 0xFFFF0000u);
    Ph[row * 256 + tid] = hh; Pl[row * 256 + tid] = ll;
}

// ============================ HMMA split-bf16 GEMM ===========================
// C[128x128] = (Ah+Al)[M,K] x (Bh+Bl)[N,K]^T  (both K-major), 3-pass hi/lo.
// Tiles: BM=128, BN=128, BK=64. 8 warps (2 M x 4 N), warp tile 64x32.
// EPI: 0 proj->hi/lo bf16 (+bias) row-major; 1 scores->fp32 masked logits;
//      2 fp32 out; 3 proj->hi/lo bf16 (+bias) transposed [h][token].
static constexpr int STAGE_BYTES = 65536;            // 4 tiles x 16KB
static constexpr int SMEM_BYTES  = 2 * STAGE_BYTES;  // 128KB

template <int EPI>
__global__ __launch_bounds__(256, 1) void gemm_hmma(
    const __nv_bfloat16* __restrict__ Ah, const __nv_bfloat16* __restrict__ Al,
    long long sA, int lda,
    const __nv_bfloat16* __restrict__ Bh, const __nv_bfloat16* __restrict__ Bl,
    long long sB, int ldb,
    int Kdim,
    float* __restrict__ Cf, long long sCf,
    __nv_bfloat16* __restrict__ Ch, __nv_bfloat16* __restrict__ Cl,
    const float* __restrict__ bias, const float* __restrict__ dagT)
{
    extern __shared__ char smem[];
    const int b = blockIdx.z;
    Ah += (long long)b * sA;  Al += (long long)b * sA;
    Bh += (long long)b * sB;  Bl += (long long)b * sB;

    const int mBase = blockIdx.y * 128;
    const int nBase = blockIdx.x * 128;
    const int tid = threadIdx.x, wid = tid >> 5, lane = tid & 31;
    const int warpM = (wid >> 2) * 64;     // 0 or 64
    const int warpN = (wid & 3) * 32;      // 0,32,64,96

    const uint32_t sb = smem_u32(smem);

    const __nv_bfloat16* srcs[4];
    srcs[0] = Ah + (long long)mBase * lda;
    srcs[1] = Al + (long long)mBase * lda;
    srcs[2] = Bh + (long long)nBase * ldb;
    srcs[3] = Bl + (long long)nBase * ldb;
    const int lds_[4] = { lda, lda, ldb, ldb };

    auto load_stage = [&](int st, int k0) {
        const uint32_t stBase = sb + st * STAGE_BYTES;
#pragma unroll
        for (int i = 0; i < 16; i++) {
            const int tile = i >> 2;
            const int idx  = ((i & 3) << 8) | tid;
            const int row  = idx >> 3;                 // 0..127
            const int k8   = (idx & 7) << 3;           // 0..56
            const __nv_bfloat16* src = srcs[tile] + (long long)row * lds_[tile] + k0 + k8;
            const uint32_t dst = stBase + tile * 16384 + SWZ128((uint32_t)(row * 128 + k8 * 2));
            CP_ASYNC16(dst, src);
        }
    };

    float acc[4][4][4];
#pragma unroll
    for (int mi = 0; mi < 4; mi++)
#pragma unroll
        for (int ni = 0; ni < 4; ni++)
#pragma unroll
            for (int c = 0; c < 4; c++) acc[mi][ni][c] = 0.0f;

    // precomputed ldmatrix lane row offsets
    const int aRow = warpM + (lane & 15);       // + mi*16
    const int bRow = warpN + (lane & 15);       // + np*16
    const int kHalf = (lane >> 4) * 8;          // k-offset within k16

    const int nch = Kdim >> 6;
    load_stage(0, 0);
    CP_COMMIT();

    for (int i = 0; i < nch; i++) {
        const int st = i & 1;
        if (i + 1 < nch) {
            load_stage(st ^ 1, (i + 1) << 6);
            CP_COMMIT();
            CP_WAIT(1);
        } else {
            CP_WAIT(0);
        }
        __syncthreads();

        const uint32_t ahB = sb + st * STAGE_BYTES;
        const uint32_t alB = ahB + 16384;
        const uint32_t bhB = ahB + 32768;
        const uint32_t blB = ahB + 49152;

#pragma unroll
        for (int ks = 0; ks < 4; ks++) {
            const int kb = (ks * 16 + kHalf) * 2;
            uint32_t ah[4][4], al[4][4], bh[4][2], bl[4][2];
#pragma unroll
            for (int mi = 0; mi < 4; mi++) {
                const uint32_t offA = SWZ128((uint32_t)((aRow + mi * 16) * 128 + kb));
                ldsm_x4(ah[mi][0], ah[mi][1], ah[mi][2], ah[mi][3], ahB + offA);
                ldsm_x4(al[mi][0], al[mi][1], al[mi][2], al[mi][3], alB + offA);
            }
#pragma unroll
            for (int np = 0; np < 2; np++) {
                const uint32_t offB = SWZ128((uint32_t)((bRow + np * 16) * 128 + kb));
                uint32_t r0, r1, r2, r3;
                ldsm_x4(r0, r1, r2, r3, bhB + offB);
                bh[np * 2 + 0][0] = r0; bh[np * 2 + 0][1] = r2;
                bh[np * 2 + 1][0] = r1; bh[np * 2 + 1][1] = r3;
                ldsm_x4(r0, r1, r2, r3, blB + offB);
                bl[np * 2 + 0][0] = r0; bl[np * 2 + 0][1] = r2;
                bl[np * 2 + 1][0] = r1; bl[np * 2 + 1][1] = r3;
            }
#pragma unroll
            for (int mi = 0; mi < 4; mi++)
#pragma unroll
                for (int ni = 0; ni < 4; ni++) {
                    mma_bf16(acc[mi][ni], ah[mi], bh[ni][0], bh[ni][1]);
                    mma_bf16(acc[mi][ni], ah[mi], bl[ni][0], bl[ni][1]);
                    mma_bf16(acc[mi][ni], al[mi], bh[ni][0], bh[ni][1]);
                }
        }
        __syncthreads();
    }

    // ---------------- epilogue: stage to smem (stride 132), then coalesced out
    uint32_t* stgU = (uint32_t*)smem;
    float*    stgF = (float*)smem;
    const int rBase = lane >> 2;          // 0..7
    const int cOff  = (lane & 3) * 2;

#pragma unroll
    for (int mi = 0; mi < 4; mi++) {
        const int r0 = warpM + mi * 16 + rBase;
        const int r1 = r0 + 8;
#pragma unroll
        for (int ni = 0; ni < 4; ni++) {
            const int col = warpN + ni * 8 + cOff;
            if (EPI == 0 || EPI == 3) {
                const float b0 = bias[nBase + col], b1 = bias[nBase + col + 1];
                const uint32_t v00 = splitpack(acc[mi][ni][0] + b0);
                const uint32_t v01 = splitpack(acc[mi][ni][1] + b1);
                const uint32_t v10 = splitpack(acc[mi][ni][2] + b0);
                const uint32_t v11 = splitpack(acc[mi][ni][3] + b1);
                if (EPI == 0) {
                    stgU[r0 * 132 + col] = v00; stgU[r0 * 132 + col + 1] = v01;
                    stgU[r1 * 132 + col] = v10; stgU[r1 * 132 + col + 1] = v11;
                } else {
                    stgU[col * 132 + r0] = v00; stgU[(col + 1) * 132 + r0] = v01;
                    stgU[col * 132 + r1] = v10; stgU[(col + 1) * 132 + r1] = v11;
                }
            } else {
                stgF[r0 * 132 + col] = acc[mi][ni][0]; stgF[r0 * 132 + col + 1] = acc[mi][ni][1];
                stgF[r1 * 132 + col] = acc[mi][ni][2]; stgF[r1 * 132 + col + 1] = acc[mi][ni][3];
            }
        }
    }
    __syncthreads();

    if (EPI == 0) {               // row-major hi/lo bf16
#pragma unroll
        for (int i = 0; i < 16; i++) {
            const int q = tid + i * 256;
            const int row = q >> 5, c4 = (q & 31) << 2;
            uint32_t w0 = stgU[row * 132 + c4], w1 = stgU[row * 132 + c4 + 1];
            uint32_t w2 = stgU[row * 132 + c4 + 2], w3 = stgU[row * 132 + c4 + 3];
            uint2 hh, ll;
            hh.x = (w0 & 0xFFFF) | (w1 << 16);  hh.y = (w2 & 0xFFFF) | (w3 << 16);
            ll.x = (w0 >> 16) | (w1 & 0xFFFF0000u);  ll.y = (w2 >> 16) | (w3 & 0xFFFF0000u);
            const long long gi = (long long)(mBase + row) * 512 + nBase + c4;
            *(uint2*)(Ch + gi) = hh;  *(uint2*)(Cl + gi) = ll;
        }
    } else if (EPI == 3) {        // transposed hi/lo bf16: out[bat][h][t]
#pragma unroll
        for (int i = 0; i < 16; i++) {
            const int q = tid + i * 256;
            const int c = q >> 5, r4 = (q & 31) << 2;
            uint32_t w0 = stgU[c * 132 + r4], w1 = stgU[c * 132 + r4 + 1];
            uint32_t w2 = stgU[c * 132 + r4 + 2], w3 = stgU[c * 132 + r4 + 3];
            uint2 hh, ll;
            hh.x = (w0 & 0xFFFF) | (w1 << 16);  hh.y = (w2 & 0xFFFF) | (w3 << 16);
            ll.x = (w0 >> 16) | (w1 & 0xFFFF0000u);  ll.y = (w2 >> 16) | (w3 & 0xFFFF0000u);
            const int gt = mBase + r4;
            const int bat = gt >> 10, t0 = gt & 1023;
            const long long gi = ((long long)bat * 512 + (nBase + c)) * 1024 + t0;
            *(uint2*)(Ch + gi) = hh;  *(uint2*)(Cl + gi) = ll;
        }
    } else if (EPI == 1) {        // scores: scale + dag mask -> fp32 logits
        const float scale = 0.044194173824159216f;   // 1/sqrt(512)
#pragma unroll
        for (int i = 0; i < 16; i++) {
            const int q = tid + i * 256;
            const int row = q >> 5, c4 = (q & 31) << 2;
            const int t = mBase + row;
            float4 dg = *(const float4*)(dagT + (long long)t * 1024 + nBase + c4);
            float v0 = stgF[row * 132 + c4]     * scale * dg.x;
            float v1 = stgF[row * 132 + c4 + 1] * scale * dg.y;
            float v2 = stgF[row * 132 + c4 + 2] * scale * dg.z;
            float v3 = stgF[row * 132 + c4 + 3] * scale * dg.w;
            float4 o;
            o.x = (v0 == 0.0f) ? NEGV : v0;
            o.y = (v1 == 0.0f) ? NEGV : v1;
            o.z = (v2 == 0.0f) ? NEGV : v2;
            o.w = (v3 == 0.0f) ? NEGV : v3;
            *(float4*)(Cf + (long long)b * sCf + (long long)t * 1024 + nBase + c4) = o;
        }
    } else {                      // EPI 2: fp32 out, ldc = 512
#pragma unroll
        for (int i = 0; i < 16; i++) {
            const int q = tid + i * 256;
            const int row = q >> 5, c4 = (q & 31) << 2;
            float4 o;
            o.x = stgF[row * 132 + c4];
            o.y = stgF[row * 132 + c4 + 1];
            o.z = stgF[row * 132 + c4 + 2];
            o.w = stgF[row * 132 + c4 + 3];
            *(float4*)(Cf + (long long)b * sCf + (long long)(mBase + row) * 512 + nBase + c4) = o;
        }
    }
}

// ============================ launch =========================================
extern "C" void kernel_launch(void* const* d_in, const int* in_sizes, int n_in,
                              void* d_out, int out_size)
{
    const float* X   = (const float*)d_in[0];
    const float* Y   = (const float*)d_in[1];
    const float* dag = (const float*)d_in[2];
    const float* Wk  = (const float*)d_in[3];
    const float* bk  = (const float*)d_in[4];
    const float* Wq  = (const float*)d_in[5];
    const float* bq  = (const float*)d_in[6];
    const float* Wv  = (const float*)d_in[7];
    const float* bv  = (const float*)d_in[8];
    float* O = (float*)d_out;

    __nv_bfloat16 *Xh, *Xl, *Yh, *Yl, *Kh, *Kl, *Qh, *Ql, *Vth, *Vtl, *Wth, *Wtl, *Ph, *Pl;
    float *S, *dagT;
    cudaGetSymbolAddress((void**)&Xh, g_Xh);   cudaGetSymbolAddress((void**)&Xl, g_Xl);
    cudaGetSymbolAddress((void**)&Yh, g_Yh);   cudaGetSymbolAddress((void**)&Yl, g_Yl);
    cudaGetSymbolAddress((void**)&Kh, g_Kh);   cudaGetSymbolAddress((void**)&Kl, g_Kl);
    cudaGetSymbolAddress((void**)&Qh, g_Qh);   cudaGetSymbolAddress((void**)&Ql, g_Ql);
    cudaGetSymbolAddress((void**)&Vth, g_Vth); cudaGetSymbolAddress((void**)&Vtl, g_Vtl);
    cudaGetSymbolAddress((void**)&Wth, g_Wth); cudaGetSymbolAddress((void**)&Wtl, g_Wtl);
    cudaGetSymbolAddress((void**)&Ph, g_Ph);   cudaGetSymbolAddress((void**)&Pl, g_Pl);
    cudaGetSymbolAddress((void**)&S, g_S);     cudaGetSymbolAddress((void**)&dagT, g_dagT);

    cudaFuncSetAttribute(gemm_hmma<0>, cudaFuncAttributeMaxDynamicSharedMemorySize, SMEM_BYTES);
    cudaFuncSetAttribute(gemm_hmma<1>, cudaFuncAttributeMaxDynamicSharedMemorySize, SMEM_BYTES);
    cudaFuncSetAttribute(gemm_hmma<2>, cudaFuncAttributeMaxDynamicSharedMemorySize, SMEM_BYTES);
    cudaFuncSetAttribute(gemm_hmma<3>, cudaFuncAttributeMaxDynamicSharedMemorySize, SMEM_BYTES);

    // ---- prep ----
    split_kernel<<<32768, 256>>>((const float4*)X, (uint2*)Xh, (uint2*)Xl);
    split_kernel<<<32768, 256>>>((const float4*)Y, (uint2*)Yh, (uint2*)Yl);
    wt_split_kernel<<<1024, 256>>>(Wk, Wth,          Wtl);
    wt_split_kernel<<<1024, 256>>>(Wq, Wth + 262144, Wtl + 262144);
    wt_split_kernel<<<1024, 256>>>(Wv, Wth + 524288, Wtl + 524288);
    dagt_kernel<<<4096, 256>>>(dag, dagT);

    dim3 blk(256);

    // ---- projections: [65536,512] x Wt[512,512]^T ----
    dim3 gproj(4, 512, 1);
    gemm_hmma<0><<<gproj, blk, SMEM_BYTES>>>(Xh, Xl, 0, 512, Wth,          Wtl,          0, 512, 512,
                                             nullptr, 0, Kh, Kl, bk, nullptr);
    gemm_hmma<0><<<gproj, blk, SMEM_BYTES>>>(Yh, Yl, 0, 512, Wth + 262144, Wtl + 262144, 0, 512, 512,
                                             nullptr, 0, Qh, Ql, bq, nullptr);
    gemm_hmma<3><<<gproj, blk, SMEM_BYTES>>>(Xh, Xl, 0, 512, Wth + 524288, Wtl + 524288, 0, 512, 512,
                                             nullptr, 0, Vth, Vtl, bv, nullptr);

    // ---- scores: per-batch Q[1024,512] x K[1024,512]^T -> masked logits ----
    dim3 gsc(8, 8, 64);
    gemm_hmma<1><<<gsc, blk, SMEM_BYTES>>>(Qh, Ql, 524288, 512, Kh, Kl, 524288, 512, 512,
                                           S, 1048576, nullptr, nullptr, nullptr, dagT);

    // ---- softmax -> probs hi/lo ----
    softmax_kernel<<<65536, 256>>>(S, (uint2*)Ph, (uint2*)Pl);

    // ---- output: per-batch P[1024,1024] x Vt[512,1024]^T -> fp32 out ----
    dim3 gav(4, 8, 64);
    gemm_hmma<2><<<gav, blk, SMEM_BYTES>>>(Ph, Pl, 1048576, 1024, Vth, Vtl, 524288, 1024, 1024,
                                           O, 524288, nullptr, nullptr, nullptr, nullptr);
}

// round 4
// speedup vs baseline: 3.1806x; 1.3183x over previous
#include <cuda_runtime.h>
#include <cuda_fp16.h>
#include <cstdint>

#define NEGV (-1e30f)

// ============================ scratch (no allocs) ============================
__device__ __half g_Xh[33554432], g_Xl[33554432];
__device__ __half g_Yh[33554432], g_Yl[33554432];
__device__ __half g_Kh[33554432];                       // K single fp16 [b][t][h]
__device__ __half g_Qh[33554432], g_Ql[33554432];
__device__ __half g_Vth[33554432];                      // V^T single fp16 [b][h][t]
__device__ float  g_S [67108864];                       // logits [b][t][s]
__device__ __half g_Ph[67108864], g_Pl[67108864];       // probs hi/lo
__device__ __half g_Wth[786432];                        // 3x W^T [h][d] single fp16
__device__ float  g_dagT[1048576];                      // dag transposed [t][s]

// ============================ PTX helpers (base sm_103 ISA) ==================
__device__ __forceinline__ uint32_t smem_u32(const void* p) {
    uint32_t a;
    asm("{ .reg .u64 t; cvta.to.shared.u64 t, %1; cvt.u32.u64 %0, t; }" : "=r"(a) : "l"(p));
    return a;
}
#define CP_ASYNC16(dst, src) \
    asm volatile("cp.async.cg.shared.global [%0], [%1], 16;" :: "r"(dst), "l"(src))
#define CP_COMMIT() asm volatile("cp.async.commit_group;" ::: "memory")
#define CP_WAIT(n)  asm volatile("cp.async.wait_group %0;" :: "n"(n) : "memory")

__device__ __forceinline__ void ldsm_x4(uint32_t& r0, uint32_t& r1, uint32_t& r2, uint32_t& r3,
                                        uint32_t addr) {
    asm volatile("ldmatrix.sync.aligned.m8n8.x4.shared.b16 {%0,%1,%2,%3}, [%4];"
                 : "=r"(r0), "=r"(r1), "=r"(r2), "=r"(r3) : "r"(addr));
}
__device__ __forceinline__ void mma_f16(float* c, const uint32_t* a, uint32_t b0, uint32_t b1) {
    asm volatile(
        "mma.sync.aligned.m16n8k16.row.col.f32.f16.f16.f32 "
        "{%0,%1,%2,%3}, {%4,%5,%6,%7}, {%8,%9}, {%0,%1,%2,%3};"
        : "+f"(c[0]), "+f"(c[1]), "+f"(c[2]), "+f"(c[3])
        : "r"(a[0]), "r"(a[1]), "r"(a[2]), "r"(a[3]), "r"(b0), "r"(b1));
}
#define SWZ128(o) ((o) ^ (((o) >> 3) & 0x70))

// ============================ small utility kernels ==========================
__device__ __forceinline__ uint32_t splitpack_h(float x) {
    __half h = __float2half_rn(x);
    float r = x - __half2float(h);
    __half l = __float2half_rn(r);
    return ((uint32_t)__half_as_ushort(l) << 16) | (uint32_t)__half_as_ushort(h);
}

__global__ __launch_bounds__(256) void split_kernel(const float4* __restrict__ src,
                                                    uint2* __restrict__ h, uint2* __restrict__ l) {
    int i = blockIdx.x * 256 + threadIdx.x;
    float4 v = src[i];
    uint32_t p0 = splitpack_h(v.x), p1 = splitpack_h(v.y), p2 = splitpack_h(v.z), p3 = splitpack_h(v.w);
    uint2 hh, ll;
    hh.x = (p0 & 0xFFFF) | (p1 << 16);  hh.y = (p2 & 0xFFFF) | (p3 << 16);
    ll.x = (p0 >> 16) | (p1 & 0xFFFF0000u);  ll.y = (p2 >> 16) | (p3 & 0xFFFF0000u);
    h[i] = hh; l[i] = ll;
}

__global__ __launch_bounds__(256) void wt_half_kernel(const float* __restrict__ W,
                                                      __half* __restrict__ th) {
    int i = blockIdx.x * 256 + threadIdx.x;           // Wt[h][d] = W[d][h]
    int hh = i >> 9, d = i & 511;
    th[i] = __float2half_rn(W[d * 512 + hh]);
}

__global__ __launch_bounds__(256) void dagt_kernel(const float* __restrict__ dag,
                                                   float* __restrict__ dagT) {
    int i = blockIdx.x * 256 + threadIdx.x;           // dagT[t][s] = dag[s][t]
    int t = i >> 10, s = i & 1023;
    dagT[i] = dag[s * 1024 + t];
}

__global__ __launch_bounds__(256) void softmax_kernel(const float* __restrict__ S,
                                                      uint2* __restrict__ Ph, uint2* __restrict__ Pl) {
    const long long row = blockIdx.x;
    const float* p = S + row * 1024;
    const int tid = threadIdx.x;
    float4 v = ((const float4*)p)[tid];

    __shared__ float red[256];
    float m = fmaxf(fmaxf(v.x, v.y), fmaxf(v.z, v.w));
    red[tid] = m; __syncthreads();
#pragma unroll
    for (int s = 128; s > 0; s >>= 1) { if (tid < s) red[tid] = fmaxf(red[tid], red[tid + s]); __syncthreads(); }
    const float mx = red[0]; __syncthreads();

    float4 e;
    e.x = __expf(v.x - mx); e.y = __expf(v.y - mx); e.z = __expf(v.z - mx); e.w = __expf(v.w - mx);
    red[tid] = e.x + e.y + e.z + e.w; __syncthreads();
#pragma unroll
    for (int s = 128; s > 0; s >>= 1) { if (tid < s) red[tid] += red[tid + s]; __syncthreads(); }
    const float inv = 1.0f / red[0];

    if (mx < -1e29f) { e.x = e.y = e.z = e.w = 0.0f; }
    else { e.x *= inv; e.y *= inv; e.z *= inv; e.w *= inv; }

    uint32_t p0 = splitpack_h(e.x), p1 = splitpack_h(e.y), p2 = splitpack_h(e.z), p3 = splitpack_h(e.w);
    uint2 hh, ll;
    hh.x = (p0 & 0xFFFF) | (p1 << 16);  hh.y = (p2 & 0xFFFF) | (p3 << 16);
    ll.x = (p0 >> 16) | (p1 & 0xFFFF0000u);  ll.y = (p2 >> 16) | (p3 & 0xFFFF0000u);
    Ph[row * 256 + tid] = hh; Pl[row * 256 + tid] = ll;
}

// ============================ HMMA 2-pass fp16 GEMM ==========================
// C[128x128] = (Ah+Al)[M,K] x B[N,K]^T   (A hi/lo fp16, B single fp16, K-major)
// Tiles: BM=128, BN=128, BK=64. 8 warps (2 M x 4 N), warp tile 64x32.
// EPI: 0 -> hi/lo fp16 (+bias) row-major          (Q)
//      4 -> single fp16 (+bias) row-major         (K)
//      3 -> single fp16 (+bias) transposed [h][t] (V^T)
//      1 -> fp32 masked logits (scale + dag)
//      2 -> fp32 out
static constexpr int STAGE_BYTES = 49152;            // 3 tiles x 16KB
static constexpr int SMEM_BYTES  = 2 * STAGE_BYTES;  // 96KB

template <int EPI>
__global__ __launch_bounds__(256, 1) void gemm_hmma(
    const __half* __restrict__ Ah, const __half* __restrict__ Al,
    long long sA, int lda,
    const __half* __restrict__ B, long long sB, int ldb,
    int Kdim,
    float* __restrict__ Cf, long long sCf,
    __half* __restrict__ Ch, __half* __restrict__ Cl,
    const float* __restrict__ bias, const float* __restrict__ dagT)
{
    extern __shared__ char smem[];
    const int b = blockIdx.z;
    Ah += (long long)b * sA;  Al += (long long)b * sA;
    B  += (long long)b * sB;

    const int mBase = blockIdx.y * 128;
    const int nBase = blockIdx.x * 128;
    const int tid = threadIdx.x, wid = tid >> 5, lane = tid & 31;
    const int warpM = (wid >> 2) * 64;     // 0 or 64
    const int warpN = (wid & 3) * 32;      // 0,32,64,96

    const uint32_t sb = smem_u32(smem);

    const __half* srcs[3];
    srcs[0] = Ah + (long long)mBase * lda;
    srcs[1] = Al + (long long)mBase * lda;
    srcs[2] = B  + (long long)nBase * ldb;
    const int lds_[3] = { lda, lda, ldb };

    auto load_stage = [&](int st, int k0) {
        const uint32_t stBase = sb + st * STAGE_BYTES;
#pragma unroll
        for (int i = 0; i < 12; i++) {
            const int tile = i >> 2;
            const int idx  = ((i & 3) << 8) | tid;
            const int row  = idx >> 3;                 // 0..127
            const int k8   = (idx & 7) << 3;           // 0..56
            const __half* src = srcs[tile] + (long long)row * lds_[tile] + k0 + k8;
            const uint32_t dst = stBase + tile * 16384 + SWZ128((uint32_t)(row * 128 + k8 * 2));
            CP_ASYNC16(dst, src);
        }
    };

    float acc[4][4][4];
#pragma unroll
    for (int mi = 0; mi < 4; mi++)
#pragma unroll
        for (int ni = 0; ni < 4; ni++)
#pragma unroll
            for (int c = 0; c < 4; c++) acc[mi][ni][c] = 0.0f;

    const int aRow  = warpM + (lane & 15);
    const int bRow  = warpN + (lane & 15);
    const int kHalf = (lane >> 4) * 8;

    const int nch = Kdim >> 6;
    load_stage(0, 0);
    CP_COMMIT();

    for (int i = 0; i < nch; i++) {
        const int st = i & 1;
        if (i + 1 < nch) {
            load_stage(st ^ 1, (i + 1) << 6);
            CP_COMMIT();
            CP_WAIT(1);
        } else {
            CP_WAIT(0);
        }
        __syncthreads();

        const uint32_t ahB = sb + st * STAGE_BYTES;
        const uint32_t alB = ahB + 16384;
        const uint32_t bB  = ahB + 32768;

#pragma unroll
        for (int ks = 0; ks < 4; ks++) {
            const int kb = (ks * 16 + kHalf) * 2;
            uint32_t ah[4][4], al[4][4], bf[4][2];
#pragma unroll
            for (int mi = 0; mi < 4; mi++) {
                const uint32_t offA = SWZ128((uint32_t)((aRow + mi * 16) * 128 + kb));
                ldsm_x4(ah[mi][0], ah[mi][1], ah[mi][2], ah[mi][3], ahB + offA);
                ldsm_x4(al[mi][0], al[mi][1], al[mi][2], al[mi][3], alB + offA);
            }
#pragma unroll
            for (int np = 0; np < 2; np++) {
                const uint32_t offB = SWZ128((uint32_t)((bRow + np * 16) * 128 + kb));
                uint32_t r0, r1, r2, r3;
                ldsm_x4(r0, r1, r2, r3, bB + offB);
                bf[np * 2 + 0][0] = r0; bf[np * 2 + 0][1] = r2;
                bf[np * 2 + 1][0] = r1; bf[np * 2 + 1][1] = r3;
            }
#pragma unroll
            for (int mi = 0; mi < 4; mi++)
#pragma unroll
                for (int ni = 0; ni < 4; ni++) {
                    mma_f16(acc[mi][ni], ah[mi], bf[ni][0], bf[ni][1]);
                    mma_f16(acc[mi][ni], al[mi], bf[ni][0], bf[ni][1]);
                }
        }
        __syncthreads();
    }

    // ---------------- epilogue: stage to smem (stride 132), coalesced out ----
    uint32_t* stgU = (uint32_t*)smem;
    float*    stgF = (float*)smem;
    const int rBase = lane >> 2;
    const int cOff  = (lane & 3) * 2;

#pragma unroll
    for (int mi = 0; mi < 4; mi++) {
        const int r0 = warpM + mi * 16 + rBase;
        const int r1 = r0 + 8;
#pragma unroll
        for (int ni = 0; ni < 4; ni++) {
            const int col = warpN + ni * 8 + cOff;
            if (EPI == 0) {
                const float b0 = bias[nBase + col], b1 = bias[nBase + col + 1];
                stgU[r0 * 132 + col]     = splitpack_h(acc[mi][ni][0] + b0);
                stgU[r0 * 132 + col + 1] = splitpack_h(acc[mi][ni][1] + b1);
                stgU[r1 * 132 + col]     = splitpack_h(acc[mi][ni][2] + b0);
                stgU[r1 * 132 + col + 1] = splitpack_h(acc[mi][ni][3] + b1);
            } else if (EPI == 4) {
                const float b0 = bias[nBase + col], b1 = bias[nBase + col + 1];
                stgU[r0 * 132 + col]     = (uint32_t)__half_as_ushort(__float2half_rn(acc[mi][ni][0] + b0));
                stgU[r0 * 132 + col + 1] = (uint32_t)__half_as_ushort(__float2half_rn(acc[mi][ni][1] + b1));
                stgU[r1 * 132 + col]     = (uint32_t)__half_as_ushort(__float2half_rn(acc[mi][ni][2] + b0));
                stgU[r1 * 132 + col + 1] = (uint32_t)__half_as_ushort(__float2half_rn(acc[mi][ni][3] + b1));
            } else if (EPI == 3) {
                const float b0 = bias[nBase + col], b1 = bias[nBase + col + 1];
                stgU[col * 132 + r0]       = (uint32_t)__half_as_ushort(__float2half_rn(acc[mi][ni][0] + b0));
                stgU[(col + 1) * 132 + r0] = (uint32_t)__half_as_ushort(__float2half_rn(acc[mi][ni][1] + b1));
                stgU[col * 132 + r1]       = (uint32_t)__half_as_ushort(__float2half_rn(acc[mi][ni][2] + b0));
                stgU[(col + 1) * 132 + r1] = (uint32_t)__half_as_ushort(__float2half_rn(acc[mi][ni][3] + b1));
            } else {
                stgF[r0 * 132 + col] = acc[mi][ni][0]; stgF[r0 * 132 + col + 1] = acc[mi][ni][1];
                stgF[r1 * 132 + col] = acc[mi][ni][2]; stgF[r1 * 132 + col + 1] = acc[mi][ni][3];
            }
        }
    }
    __syncthreads();

    if (EPI == 0) {               // row-major hi/lo fp16
#pragma unroll
        for (int i = 0; i < 16; i++) {
            const int q = tid + i * 256;
            const int row = q >> 5, c4 = (q & 31) << 2;
            uint32_t w0 = stgU[row * 132 + c4], w1 = stgU[row * 132 + c4 + 1];
            uint32_t w2 = stgU[row * 132 + c4 + 2], w3 = stgU[row * 132 + c4 + 3];
            uint2 hh, ll;
            hh.x = (w0 & 0xFFFF) | (w1 << 16);  hh.y = (w2 & 0xFFFF) | (w3 << 16);
            ll.x = (w0 >> 16) | (w1 & 0xFFFF0000u);  ll.y = (w2 >> 16) | (w3 & 0xFFFF0000u);
            const long long gi = (long long)(mBase + row) * 512 + nBase + c4;
            *(uint2*)(Ch + gi) = hh;  *(uint2*)(Cl + gi) = ll;
        }
    } else if (EPI == 4) {        // row-major single fp16
#pragma unroll
        for (int i = 0; i < 16; i++) {
            const int q = tid + i * 256;
            const int row = q >> 5, c4 = (q & 31) << 2;
            uint32_t w0 = stgU[row * 132 + c4], w1 = stgU[row * 132 + c4 + 1];
            uint32_t w2 = stgU[row * 132 + c4 + 2], w3 = stgU[row * 132 + c4 + 3];
            uint2 hh;
            hh.x = (w0 & 0xFFFF) | (w1 << 16);  hh.y = (w2 & 0xFFFF) | (w3 << 16);
            const long long gi = (long long)(mBase + row) * 512 + nBase + c4;
            *(uint2*)(Ch + gi) = hh;
        }
    } else if (EPI == 3) {        // transposed single fp16: out[bat][h][t]
#pragma unroll
        for (int i = 0; i < 16; i++) {
            const int q = tid + i * 256;
            const int c = q >> 5, r4 = (q & 31) << 2;
            uint32_t w0 = stgU[c * 132 + r4], w1 = stgU[c * 132 + r4 + 1];
            uint32_t w2 = stgU[c * 132 + r4 + 2], w3 = stgU[c * 132 + r4 + 3];
            uint2 hh;
            hh.x = (w0 & 0xFFFF) | (w1 << 16);  hh.y = (w2 & 0xFFFF) | (w3 << 16);
            const int gt = mBase + r4;
            const int bat = gt >> 10, t0 = gt & 1023;
            const long long gi = ((long long)bat * 512 + (nBase + c)) * 1024 + t0;
            *(uint2*)(Ch + gi) = hh;
        }
    } else if (EPI == 1) {        // scores: scale + dag mask -> fp32 logits
        const float scale = 0.044194173824159216f;   // 1/sqrt(512)
#pragma unroll
        for (int i = 0; i < 16; i++) {
            const int q = tid + i * 256;
            const int row = q >> 5, c4 = (q & 31) << 2;
            const int t = mBase + row;
            float4 dg = *(const float4*)(dagT + (long long)t * 1024 + nBase + c4);
            float v0 = stgF[row * 132 + c4]     * scale * dg.x;
            float v1 = stgF[row * 132 + c4 + 1] * scale * dg.y;
            float v2 = stgF[row * 132 + c4 + 2] * scale * dg.z;
            float v3 = stgF[row * 132 + c4 + 3] * scale * dg.w;
            float4 o;
            o.x = (v0 == 0.0f) ? NEGV : v0;
            o.y = (v1 == 0.0f) ? NEGV : v1;
            o.z = (v2 == 0.0f) ? NEGV : v2;
            o.w = (v3 == 0.0f) ? NEGV : v3;
            *(float4*)(Cf + (long long)b * sCf + (long long)t * 1024 + nBase + c4) = o;
        }
    } else {                      // EPI 2: fp32 out, ldc = 512
#pragma unroll
        for (int i = 0; i < 16; i++) {
            const int q = tid + i * 256;
            const int row = q >> 5, c4 = (q & 31) << 2;
            float4 o;
            o.x = stgF[row * 132 + c4];
            o.y = stgF[row * 132 + c4 + 1];
            o.z = stgF[row * 132 + c4 + 2];
            o.w = stgF[row * 132 + c4 + 3];
            *(float4*)(Cf + (long long)b * sCf + (long long)(mBase + row) * 512 + nBase + c4) = o;
        }
    }
}

// ============================ launch =========================================
extern "C" void kernel_launch(void* const* d_in, const int* in_sizes, int n_in,
                              void* d_out, int out_size)
{
    const float* X   = (const float*)d_in[0];
    const float* Y   = (const float*)d_in[1];
    const float* dag = (const float*)d_in[2];
    const float* Wk  = (const float*)d_in[3];
    const float* bk  = (const float*)d_in[4];
    const float* Wq  = (const float*)d_in[5];
    const float* bq  = (const float*)d_in[6];
    const float* Wv  = (const float*)d_in[7];
    const float* bv  = (const float*)d_in[8];
    float* O = (float*)d_out;

    __half *Xh, *Xl, *Yh, *Yl, *Kh, *Qh, *Ql, *Vth, *Wth, *Ph, *Pl;
    float *S, *dagT;
    cudaGetSymbolAddress((void**)&Xh, g_Xh);   cudaGetSymbolAddress((void**)&Xl, g_Xl);
    cudaGetSymbolAddress((void**)&Yh, g_Yh);   cudaGetSymbolAddress((void**)&Yl, g_Yl);
    cudaGetSymbolAddress((void**)&Kh, g_Kh);
    cudaGetSymbolAddress((void**)&Qh, g_Qh);   cudaGetSymbolAddress((void**)&Ql, g_Ql);
    cudaGetSymbolAddress((void**)&Vth, g_Vth);
    cudaGetSymbolAddress((void**)&Wth, g_Wth);
    cudaGetSymbolAddress((void**)&Ph, g_Ph);   cudaGetSymbolAddress((void**)&Pl, g_Pl);
    cudaGetSymbolAddress((void**)&S, g_S);     cudaGetSymbolAddress((void**)&dagT, g_dagT);

    cudaFuncSetAttribute(gemm_hmma<0>, cudaFuncAttributeMaxDynamicSharedMemorySize, SMEM_BYTES);
    cudaFuncSetAttribute(gemm_hmma<1>, cudaFuncAttributeMaxDynamicSharedMemorySize, SMEM_BYTES);
    cudaFuncSetAttribute(gemm_hmma<2>, cudaFuncAttributeMaxDynamicSharedMemorySize, SMEM_BYTES);
    cudaFuncSetAttribute(gemm_hmma<3>, cudaFuncAttributeMaxDynamicSharedMemorySize, SMEM_BYTES);
    cudaFuncSetAttribute(gemm_hmma<4>, cudaFuncAttributeMaxDynamicSharedMemorySize, SMEM_BYTES);

    // ---- prep ----
    split_kernel<<<32768, 256>>>((const float4*)X, (uint2*)Xh, (uint2*)Xl);
    split_kernel<<<32768, 256>>>((const float4*)Y, (uint2*)Yh, (uint2*)Yl);
    wt_half_kernel<<<1024, 256>>>(Wk, Wth);
    wt_half_kernel<<<1024, 256>>>(Wq, Wth + 262144);
    wt_half_kernel<<<1024, 256>>>(Wv, Wth + 524288);
    dagt_kernel<<<4096, 256>>>(dag, dagT);

    dim3 blk(256);

    // ---- projections: [65536,512] x Wt[512,512]^T ----
    dim3 gproj(4, 512, 1);
    gemm_hmma<4><<<gproj, blk, SMEM_BYTES>>>(Xh, Xl, 0, 512, Wth,          0, 512, 512,
                                             nullptr, 0, Kh, nullptr, bk, nullptr);
    gemm_hmma<0><<<gproj, blk, SMEM_BYTES>>>(Yh, Yl, 0, 512, Wth + 262144, 0, 512, 512,
                                             nullptr, 0, Qh, Ql, bq, nullptr);
    gemm_hmma<3><<<gproj, blk, SMEM_BYTES>>>(Xh, Xl, 0, 512, Wth + 524288, 0, 512, 512,
                                             nullptr, 0, Vth, nullptr, bv, nullptr);

    // ---- scores: per-batch Q[1024,512] x K[1024,512]^T -> masked logits ----
    dim3 gsc(8, 8, 64);
    gemm_hmma<1><<<gsc, blk, SMEM_BYTES>>>(Qh, Ql, 524288, 512, Kh, 524288, 512, 512,
                                           S, 1048576, nullptr, nullptr, nullptr, dagT);

    // ---- softmax -> probs hi/lo fp16 ----
    softmax_kernel<<<65536, 256>>>(S, (uint2*)Ph, (uint2*)Pl);

    // ---- output: per-batch P[1024,1024] x Vt[512,1024]^T -> fp32 out ----
    dim3 gav(4, 8, 64);
    gemm_hmma<2><<<gav, blk, SMEM_BYTES>>>(Ph, Pl, 1048576, 1024, Vth, 524288, 1024, 1024,
                                           O, 524288, nullptr, nullptr, nullptr, nullptr);
}

// round 5
// speedup vs baseline: 3.3616x; 1.0569x over previous
#include <cuda_runtime.h>
#include <cuda_fp16.h>
#include <cstdint>

#define NEGV (-1e30f)

// ============================ scratch (no allocs) ============================
__device__ __half g_Xh[33554432], g_Xl[33554432];
__device__ __half g_Yh[33554432], g_Yl[33554432];
__device__ __half g_Kh[33554432];                       // K single fp16 [b][t][h]
__device__ __half g_Qh[33554432], g_Ql[33554432];
__device__ __half g_Vth[33554432];                      // V^T single fp16 [b][h][t]
__device__ float  g_S [67108864];                       // logits [b][t][s]
__device__ __half g_Ph[67108864], g_Pl[67108864];       // probs hi/lo
__device__ __half g_Wth[786432];                        // 3x W^T [h][d] single fp16
__device__ float  g_dagT[1048576];                      // dag transposed [t][s]

// ============================ PTX helpers (base sm_103 ISA) ==================
__device__ __forceinline__ uint32_t smem_u32(const void* p) {
    uint32_t a;
    asm("{ .reg .u64 t; cvta.to.shared.u64 t, %1; cvt.u32.u64 %0, t; }" : "=r"(a) : "l"(p));
    return a;
}
#define CP_ASYNC16(dst, src) \
    asm volatile("cp.async.cg.shared.global [%0], [%1], 16;" :: "r"(dst), "l"(src))
#define CP_COMMIT() asm volatile("cp.async.commit_group;" ::: "memory")
#define CP_WAIT(n)  asm volatile("cp.async.wait_group %0;" :: "n"(n) : "memory")

__device__ __forceinline__ void ldsm_x4(uint32_t& r0, uint32_t& r1, uint32_t& r2, uint32_t& r3,
                                        uint32_t addr) {
    asm volatile("ldmatrix.sync.aligned.m8n8.x4.shared.b16 {%0,%1,%2,%3}, [%4];"
                 : "=r"(r0), "=r"(r1), "=r"(r2), "=r"(r3) : "r"(addr));
}
__device__ __forceinline__ void mma_f16(float* c, const uint32_t* a, uint32_t b0, uint32_t b1) {
    asm volatile(
        "mma.sync.aligned.m16n8k16.row.col.f32.f16.f16.f32 "
        "{%0,%1,%2,%3}, {%4,%5,%6,%7}, {%8,%9}, {%0,%1,%2,%3};"
        : "+f"(c[0]), "+f"(c[1]), "+f"(c[2]), "+f"(c[3])
        : "r"(a[0]), "r"(a[1]), "r"(a[2]), "r"(a[3]), "r"(b0), "r"(b1));
}
#define SWZ128(o) ((o) ^ (((o) >> 3) & 0x70))

// ============================ small utility kernels ==========================
__device__ __forceinline__ uint32_t splitpack_h(float x) {
    __half h = __float2half_rn(x);
    float r = x - __half2float(h);
    __half l = __float2half_rn(r);
    return ((uint32_t)__half_as_ushort(l) << 16) | (uint32_t)__half_as_ushort(h);
}

__global__ __launch_bounds__(256) void split_kernel(const float4* __restrict__ src,
                                                    uint2* __restrict__ h, uint2* __restrict__ l) {
    int i = blockIdx.x * 256 + threadIdx.x;
    float4 v = src[i];
    uint32_t p0 = splitpack_h(v.x), p1 = splitpack_h(v.y), p2 = splitpack_h(v.z), p3 = splitpack_h(v.w);
    uint2 hh, ll;
    hh.x = (p0 & 0xFFFF) | (p1 << 16);  hh.y = (p2 & 0xFFFF) | (p3 << 16);
    ll.x = (p0 >> 16) | (p1 & 0xFFFF0000u);  ll.y = (p2 >> 16) | (p3 & 0xFFFF0000u);
    h[i] = hh; l[i] = ll;
}

__global__ __launch_bounds__(256) void wt_half_kernel(const float* __restrict__ W,
                                                      __half* __restrict__ th) {
    int i = blockIdx.x * 256 + threadIdx.x;           // Wt[h][d] = W[d][h]
    int hh = i >> 9, d = i & 511;
    th[i] = __float2half_rn(W[d * 512 + hh]);
}

__global__ __launch_bounds__(256) void dagt_kernel(const float* __restrict__ dag,
                                                   float* __restrict__ dagT) {
    int i = blockIdx.x * 256 + threadIdx.x;           // dagT[t][s] = dag[s][t]
    int t = i >> 10, s = i & 1023;
    dagT[i] = dag[s * 1024 + t];
}

__global__ __launch_bounds__(256) void softmax_kernel(const float* __restrict__ S,
                                                      uint2* __restrict__ Ph, uint2* __restrict__ Pl) {
    const long long row = blockIdx.x;
    const float* p = S + row * 1024;
    const int tid = threadIdx.x;
    float4 v = ((const float4*)p)[tid];

    __shared__ float red[256];
    float m = fmaxf(fmaxf(v.x, v.y), fmaxf(v.z, v.w));
    red[tid] = m; __syncthreads();
#pragma unroll
    for (int s = 128; s > 0; s >>= 1) { if (tid < s) red[tid] = fmaxf(red[tid], red[tid + s]); __syncthreads(); }
    const float mx = red[0]; __syncthreads();

    float4 e;
    e.x = __expf(v.x - mx); e.y = __expf(v.y - mx); e.z = __expf(v.z - mx); e.w = __expf(v.w - mx);
    red[tid] = e.x + e.y + e.z + e.w; __syncthreads();
#pragma unroll
    for (int s = 128; s > 0; s >>= 1) { if (tid < s) red[tid] += red[tid + s]; __syncthreads(); }
    const float inv = 1.0f / red[0];

    if (mx < -1e29f) { e.x = e.y = e.z = e.w = 0.0f; }
    else { e.x *= inv; e.y *= inv; e.z *= inv; e.w *= inv; }

    uint32_t p0 = splitpack_h(e.x), p1 = splitpack_h(e.y), p2 = splitpack_h(e.z), p3 = splitpack_h(e.w);
    uint2 hh, ll;
    hh.x = (p0 & 0xFFFF) | (p1 << 16);  hh.y = (p2 & 0xFFFF) | (p3 << 16);
    ll.x = (p0 >> 16) | (p1 & 0xFFFF0000u);  ll.y = (p2 >> 16) | (p3 & 0xFFFF0000u);
    Ph[row * 256 + tid] = hh; Pl[row * 256 + tid] = ll;
}

// ============================ HMMA 2-pass fp16 GEMM ==========================
// C[256x128 CTA tile] = (Ah+Al)[M,K] x B[N,K]^T   (A hi/lo fp16, B fp16, K-major)
// 8 warps as 4(M) x 2(N); warp tile 64x64. BK=64, 2-stage cp.async.
// EPI: 0 hi/lo fp16 (+bias) row-major (Q); 4 single fp16 (+bias) row-major (K);
//      3 single fp16 (+bias) transposed [h][t] (V^T); 1 fp32 masked logits; 2 fp32 out.
static constexpr int STAGE_BYTES = 81920;            // Ah 32K + Al 32K + B 16K
static constexpr int SMEM_BYTES  = 2 * STAGE_BYTES;  // 160KB

template <int EPI>
__global__ __launch_bounds__(256, 1) void gemm_hmma(
    const __half* __restrict__ Ah, const __half* __restrict__ Al,
    long long sA, int lda,
    const __half* __restrict__ B, long long sB, int ldb,
    int Kdim,
    float* __restrict__ Cf, long long sCf,
    __half* __restrict__ Ch, __half* __restrict__ Cl,
    const float* __restrict__ bias, const float* __restrict__ dagT)
{
    extern __shared__ char smem[];
    const int b = blockIdx.z;
    Ah += (long long)b * sA;  Al += (long long)b * sA;
    B  += (long long)b * sB;

    const int mBase = blockIdx.y * 256;
    const int nBase = blockIdx.x * 128;
    const int tid = threadIdx.x, wid = tid >> 5, lane = tid & 31;
    const int warpM = (wid >> 1) * 64;     // 0,64,128,192
    const int warpN = (wid & 1) * 64;      // 0,64

    const uint32_t sb = smem_u32(smem);

    const __half* srcAh = Ah + (long long)mBase * lda;
    const __half* srcAl = Al + (long long)mBase * lda;
    const __half* srcB  = B  + (long long)nBase * ldb;

    auto load_stage = [&](int st, int k0) {
        const uint32_t stBase = sb + st * STAGE_BYTES;
#pragma unroll
        for (int i = 0; i < 8; i++) {              // Ah: 256 rows x 8 chunks
            const int idx = (i << 8) | tid;
            const int row = idx >> 3, k8 = (idx & 7) << 3;
            CP_ASYNC16(stBase + SWZ128((uint32_t)(row * 128 + k8 * 2)),
                       srcAh + (long long)row * lda + k0 + k8);
        }
#pragma unroll
        for (int i = 0; i < 8; i++) {              // Al
            const int idx = (i << 8) | tid;
            const int row = idx >> 3, k8 = (idx & 7) << 3;
            CP_ASYNC16(stBase + 32768 + SWZ128((uint32_t)(row * 128 + k8 * 2)),
                       srcAl + (long long)row * lda + k0 + k8);
        }
#pragma unroll
        for (int i = 0; i < 4; i++) {              // B: 128 rows x 8 chunks
            const int idx = (i << 8) | tid;
            const int row = idx >> 3, k8 = (idx & 7) << 3;
            CP_ASYNC16(stBase + 65536 + SWZ128((uint32_t)(row * 128 + k8 * 2)),
                       srcB + (long long)row * ldb + k0 + k8);
        }
    };

    float acc[4][8][4];
#pragma unroll
    for (int mi = 0; mi < 4; mi++)
#pragma unroll
        for (int ni = 0; ni < 8; ni++)
#pragma unroll
            for (int c = 0; c < 4; c++) acc[mi][ni][c] = 0.0f;

    const int aRow  = warpM + (lane & 15);
    const int bRow  = warpN + (lane & 15);
    const int kHalf = (lane >> 4) * 8;

    const int nch = Kdim >> 6;
    load_stage(0, 0);
    CP_COMMIT();

    for (int i = 0; i < nch; i++) {
        const int st = i & 1;
        if (i + 1 < nch) {
            load_stage(st ^ 1, (i + 1) << 6);
            CP_COMMIT();
            CP_WAIT(1);
        } else {
            CP_WAIT(0);
        }
        __syncthreads();

        const uint32_t ahB = sb + st * STAGE_BYTES;
        const uint32_t alB = ahB + 32768;
        const uint32_t bB  = ahB + 65536;

#pragma unroll
        for (int ks = 0; ks < 4; ks++) {
            const int kb = (ks * 16 + kHalf) * 2;
            uint32_t bf[8][2];
#pragma unroll
            for (int np = 0; np < 4; np++) {
                const uint32_t offB = SWZ128((uint32_t)((bRow + np * 16) * 128 + kb));
                uint32_t r0, r1, r2, r3;
                ldsm_x4(r0, r1, r2, r3, bB + offB);
                bf[np * 2 + 0][0] = r0; bf[np * 2 + 0][1] = r2;
                bf[np * 2 + 1][0] = r1; bf[np * 2 + 1][1] = r3;
            }
            uint32_t af[4][4];
#pragma unroll
            for (int mi = 0; mi < 4; mi++) {
                const uint32_t offA = SWZ128((uint32_t)((aRow + mi * 16) * 128 + kb));
                ldsm_x4(af[mi][0], af[mi][1], af[mi][2], af[mi][3], ahB + offA);
            }
#pragma unroll
            for (int mi = 0; mi < 4; mi++)
#pragma unroll
                for (int ni = 0; ni < 8; ni++)
                    mma_f16(acc[mi][ni], af[mi], bf[ni][0], bf[ni][1]);
#pragma unroll
            for (int mi = 0; mi < 4; mi++) {
                const uint32_t offA = SWZ128((uint32_t)((aRow + mi * 16) * 128 + kb));
                ldsm_x4(af[mi][0], af[mi][1], af[mi][2], af[mi][3], alB + offA);
            }
#pragma unroll
            for (int mi = 0; mi < 4; mi++)
#pragma unroll
                for (int ni = 0; ni < 8; ni++)
                    mma_f16(acc[mi][ni], af[mi], bf[ni][0], bf[ni][1]);
        }
        __syncthreads();
    }

    // ---------------- epilogue: stage to smem, coalesced out -----------------
    // normal staging: 256 rows x stride 132 (u32/f32); transposed: 128 x stride 260
    uint32_t* stgU = (uint32_t*)smem;
    float*    stgF = (float*)smem;
    const int rBase = lane >> 2;
    const int cOff  = (lane & 3) * 2;

#pragma unroll
    for (int mi = 0; mi < 4; mi++) {
        const int r0 = warpM + mi * 16 + rBase;
        const int r1 = r0 + 8;
#pragma unroll
        for (int ni = 0; ni < 8; ni++) {
            const int col = warpN + ni * 8 + cOff;
            if (EPI == 0) {
                const float b0 = bias[nBase + col], b1 = bias[nBase + col + 1];
                stgU[r0 * 132 + col]     = splitpack_h(acc[mi][ni][0] + b0);
                stgU[r0 * 132 + col + 1] = splitpack_h(acc[mi][ni][1] + b1);
                stgU[r1 * 132 + col]     = splitpack_h(acc[mi][ni][2] + b0);
                stgU[r1 * 132 + col + 1] = splitpack_h(acc[mi][ni][3] + b1);
            } else if (EPI == 4) {
                const float b0 = bias[nBase + col], b1 = bias[nBase + col + 1];
                stgU[r0 * 132 + col]     = (uint32_t)__half_as_ushort(__float2half_rn(acc[mi][ni][0] + b0));
                stgU[r0 * 132 + col + 1] = (uint32_t)__half_as_ushort(__float2half_rn(acc[mi][ni][1] + b1));
                stgU[r1 * 132 + col]     = (uint32_t)__half_as_ushort(__float2half_rn(acc[mi][ni][2] + b0));
                stgU[r1 * 132 + col + 1] = (uint32_t)__half_as_ushort(__float2half_rn(acc[mi][ni][3] + b1));
            } else if (EPI == 3) {
                const float b0 = bias[nBase + col], b1 = bias[nBase + col + 1];
                stgU[col * 260 + r0]       = (uint32_t)__half_as_ushort(__float2half_rn(acc[mi][ni][0] + b0));
                stgU[(col + 1) * 260 + r0] = (uint32_t)__half_as_ushort(__float2half_rn(acc[mi][ni][1] + b1));
                stgU[col * 260 + r1]       = (uint32_t)__half_as_ushort(__float2half_rn(acc[mi][ni][2] + b0));
                stgU[(col + 1) * 260 + r1] = (uint32_t)__half_as_ushort(__float2half_rn(acc[mi][ni][3] + b1));
            } else {
                stgF[r0 * 132 + col] = acc[mi][ni][0]; stgF[r0 * 132 + col + 1] = acc[mi][ni][1];
                stgF[r1 * 132 + col] = acc[mi][ni][2]; stgF[r1 * 132 + col + 1] = acc[mi][ni][3];
            }
        }
    }
    __syncthreads();

    if (EPI == 0) {               // row-major hi/lo fp16
#pragma unroll
        for (int i = 0; i < 32; i++) {
            const int q = tid + i * 256;
            const int row = q >> 5, c4 = (q & 31) << 2;
            uint32_t w0 = stgU[row * 132 + c4], w1 = stgU[row * 132 + c4 + 1];
            uint32_t w2 = stgU[row * 132 + c4 + 2], w3 = stgU[row * 132 + c4 + 3];
            uint2 hh, ll;
            hh.x = (w0 & 0xFFFF) | (w1 << 16);  hh.y = (w2 & 0xFFFF) | (w3 << 16);
            ll.x = (w0 >> 16) | (w1 & 0xFFFF0000u);  ll.y = (w2 >> 16) | (w3 & 0xFFFF0000u);
            const long long gi = (long long)(mBase + row) * 512 + nBase + c4;
            *(uint2*)(Ch + gi) = hh;  *(uint2*)(Cl + gi) = ll;
        }
    } else if (EPI == 4) {        // row-major single fp16
#pragma unroll
        for (int i = 0; i < 32; i++) {
            const int q = tid + i * 256;
            const int row = q >> 5, c4 = (q & 31) << 2;
            uint32_t w0 = stgU[row * 132 + c4], w1 = stgU[row * 132 + c4 + 1];
            uint32_t w2 = stgU[row * 132 + c4 + 2], w3 = stgU[row * 132 + c4 + 3];
            uint2 hh;
            hh.x = (w0 & 0xFFFF) | (w1 << 16);  hh.y = (w2 & 0xFFFF) | (w3 << 16);
            const long long gi = (long long)(mBase + row) * 512 + nBase + c4;
            *(uint2*)(Ch + gi) = hh;
        }
    } else if (EPI == 3) {        // transposed single fp16: out[bat][h][t]
#pragma unroll
        for (int i = 0; i < 32; i++) {
            const int q = tid + i * 256;
            const int c = q >> 6, r4 = (q & 63) << 2;     // c 0..127, r4 0..252
            uint32_t w0 = stgU[c * 260 + r4], w1 = stgU[c * 260 + r4 + 1];
            uint32_t w2 = stgU[c * 260 + r4 + 2], w3 = stgU[c * 260 + r4 + 3];
            uint2 hh;
            hh.x = (w0 & 0xFFFF) | (w1 << 16);  hh.y = (w2 & 0xFFFF) | (w3 << 16);
            const int gt = mBase + r4;
            const int bat = gt >> 10, t0 = gt & 1023;
            const long long gi = ((long long)bat * 512 + (nBase + c)) * 1024 + t0;
            *(uint2*)(Ch + gi) = hh;
        }
    } else if (EPI == 1) {        // scores: scale + dag mask -> fp32 logits
        const float scale = 0.044194173824159216f;   // 1/sqrt(512)
#pragma unroll
        for (int i = 0; i < 32; i++) {
            const int q = tid + i * 256;
            const int row = q >> 5, c4 = (q & 31) << 2;
            const int t = mBase + row;
            float4 dg = *(const float4*)(dagT + (long long)t * 1024 + nBase + c4);
            float v0 = stgF[row * 132 + c4]     * scale * dg.x;
            float v1 = stgF[row * 132 + c4 + 1] * scale * dg.y;
            float v2 = stgF[row * 132 + c4 + 2] * scale * dg.z;
            float v3 = stgF[row * 132 + c4 + 3] * scale * dg.w;
            float4 o;
            o.x = (v0 == 0.0f) ? NEGV : v0;
            o.y = (v1 == 0.0f) ? NEGV : v1;
            o.z = (v2 == 0.0f) ? NEGV : v2;
            o.w = (v3 == 0.0f) ? NEGV : v3;
            *(float4*)(Cf + (long long)b * sCf + (long long)t * 1024 + nBase + c4) = o;
        }
    } else {                      // EPI 2: fp32 out, ldc = 512
#pragma unroll
        for (int i = 0; i < 32; i++) {
            const int q = tid + i * 256;
            const int row = q >> 5, c4 = (q & 31) << 2;
            float4 o;
            o.x = stgF[row * 132 + c4];
            o.y = stgF[row * 132 + c4 + 1];
            o.z = stgF[row * 132 + c4 + 2];
            o.w = stgF[row * 132 + c4 + 3];
            *(float4*)(Cf + (long long)b * sCf + (long long)(mBase + row) * 512 + nBase + c4) = o;
        }
    }
}

// ============================ launch =========================================
extern "C" void kernel_launch(void* const* d_in, const int* in_sizes, int n_in,
                              void* d_out, int out_size)
{
    const float* X   = (const float*)d_in[0];
    const float* Y   = (const float*)d_in[1];
    const float* dag = (const float*)d_in[2];
    const float* Wk  = (const float*)d_in[3];
    const float* bk  = (const float*)d_in[4];
    const float* Wq  = (const float*)d_in[5];
    const float* bq  = (const float*)d_in[6];
    const float* Wv  = (const float*)d_in[7];
    const float* bv  = (const float*)d_in[8];
    float* O = (float*)d_out;

    __half *Xh, *Xl, *Yh, *Yl, *Kh, *Qh, *Ql, *Vth, *Wth, *Ph, *Pl;
    float *S, *dagT;
    cudaGetSymbolAddress((void**)&Xh, g_Xh);   cudaGetSymbolAddress((void**)&Xl, g_Xl);
    cudaGetSymbolAddress((void**)&Yh, g_Yh);   cudaGetSymbolAddress((void**)&Yl, g_Yl);
    cudaGetSymbolAddress((void**)&Kh, g_Kh);
    cudaGetSymbolAddress((void**)&Qh, g_Qh);   cudaGetSymbolAddress((void**)&Ql, g_Ql);
    cudaGetSymbolAddress((void**)&Vth, g_Vth);
    cudaGetSymbolAddress((void**)&Wth, g_Wth);
    cudaGetSymbolAddress((void**)&Ph, g_Ph);   cudaGetSymbolAddress((void**)&Pl, g_Pl);
    cudaGetSymbolAddress((void**)&S, g_S);     cudaGetSymbolAddress((void**)&dagT, g_dagT);

    cudaFuncSetAttribute(gemm_hmma<0>, cudaFuncAttributeMaxDynamicSharedMemorySize, SMEM_BYTES);
    cudaFuncSetAttribute(gemm_hmma<1>, cudaFuncAttributeMaxDynamicSharedMemorySize, SMEM_BYTES);
    cudaFuncSetAttribute(gemm_hmma<2>, cudaFuncAttributeMaxDynamicSharedMemorySize, SMEM_BYTES);
    cudaFuncSetAttribute(gemm_hmma<3>, cudaFuncAttributeMaxDynamicSharedMemorySize, SMEM_BYTES);
    cudaFuncSetAttribute(gemm_hmma<4>, cudaFuncAttributeMaxDynamicSharedMemorySize, SMEM_BYTES);

    // ---- prep ----
    split_kernel<<<32768, 256>>>((const float4*)X, (uint2*)Xh, (uint2*)Xl);
    split_kernel<<<32768, 256>>>((const float4*)Y, (uint2*)Yh, (uint2*)Yl);
    wt_half_kernel<<<1024, 256>>>(Wk, Wth);
    wt_half_kernel<<<1024, 256>>>(Wq, Wth + 262144);
    wt_half_kernel<<<1024, 256>>>(Wv, Wth + 524288);
    dagt_kernel<<<4096, 256>>>(dag, dagT);

    dim3 blk(256);

    // ---- projections: [65536,512] x Wt[512,512]^T  (M-tiles 256, N-tiles 4) --
    dim3 gproj(4, 256, 1);
    gemm_hmma<4><<<gproj, blk, SMEM_BYTES>>>(Xh, Xl, 0, 512, Wth,          0, 512, 512,
                                             nullptr, 0, Kh, nullptr, bk, nullptr);
    gemm_hmma<0><<<gproj, blk, SMEM_BYTES>>>(Yh, Yl, 0, 512, Wth + 262144, 0, 512, 512,
                                             nullptr, 0, Qh, Ql, bq, nullptr);
    gemm_hmma<3><<<gproj, blk, SMEM_BYTES>>>(Xh, Xl, 0, 512, Wth + 524288, 0, 512, 512,
                                             nullptr, 0, Vth, nullptr, bv, nullptr);

    // ---- scores: per-batch Q[1024,512] x K[1024,512]^T -> masked logits -----
    dim3 gsc(8, 4, 64);
    gemm_hmma<1><<<gsc, blk, SMEM_BYTES>>>(Qh, Ql, 524288, 512, Kh, 524288, 512, 512,
                                           S, 1048576, nullptr, nullptr, nullptr, dagT);

    // ---- softmax -> probs hi/lo fp16 ----
    softmax_kernel<<<65536, 256>>>(S, (uint2*)Ph, (uint2*)Pl);

    // ---- output: per-batch P[1024,1024] x Vt[512,1024]^T -> fp32 out --------
    dim3 gav(4, 4, 64);
    gemm_hmma<2><<<gav, blk, SMEM_BYTES>>>(Ph, Pl, 1048576, 1024, Vth, 524288, 1024, 1024,
                                           O, 524288, nullptr, nullptr, nullptr, nullptr);
}

// round 6
// speedup vs baseline: 4.2824x; 1.2739x over previous
#include <cuda_runtime.h>
#include <cuda_fp16.h>
#include <cstdint>

#define NEGV (-1e30f)

// ============================ scratch (no allocs) ============================
__device__ __half g_Xh[33554432];                       // X single fp16
__device__ __half g_Yh[33554432], g_Yl[33554432];       // Y hi/lo
__device__ __half g_Kh[33554432];                       // K single fp16 [b][t][h]
__device__ __half g_Qh[33554432], g_Ql[33554432];       // Q hi/lo
__device__ __half g_Vth[33554432];                      // V^T single fp16 [b][h][t]
__device__ float  g_S [67108864];                       // logits [b][t][s]
__device__ __half g_Ph[67108864];                       // probs single fp16
__device__ __half g_Wth[786432];                        // 3x W^T [h][d] single fp16
__device__ float  g_dagT[1048576];                      // dag transposed [t][s]

// ============================ PTX helpers (base sm_103 ISA) ==================
__device__ __forceinline__ uint32_t smem_u32(const void* p) {
    uint32_t a;
    asm("{ .reg .u64 t; cvta.to.shared.u64 t, %1; cvt.u32.u64 %0, t; }" : "=r"(a) : "l"(p));
    return a;
}
#define CP_ASYNC16(dst, src) \
    asm volatile("cp.async.cg.shared.global [%0], [%1], 16;" :: "r"(dst), "l"(src))
#define CP_COMMIT() asm volatile("cp.async.commit_group;" ::: "memory")
#define CP_WAIT(n)  asm volatile("cp.async.wait_group %0;" :: "n"(n) : "memory")

__device__ __forceinline__ void ldsm_x4(uint32_t& r0, uint32_t& r1, uint32_t& r2, uint32_t& r3,
                                        uint32_t addr) {
    asm volatile("ldmatrix.sync.aligned.m8n8.x4.shared.b16 {%0,%1,%2,%3}, [%4];"
                 : "=r"(r0), "=r"(r1), "=r"(r2), "=r"(r3) : "r"(addr));
}
__device__ __forceinline__ void mma_f16(float* c, const uint32_t* a, uint32_t b0, uint32_t b1) {
    asm volatile(
        "mma.sync.aligned.m16n8k16.row.col.f32.f16.f16.f32 "
        "{%0,%1,%2,%3}, {%4,%5,%6,%7}, {%8,%9}, {%0,%1,%2,%3};"
        : "+f"(c[0]), "+f"(c[1]), "+f"(c[2]), "+f"(c[3])
        : "r"(a[0]), "r"(a[1]), "r"(a[2]), "r"(a[3]), "r"(b0), "r"(b1));
}
#define SWZ128(o) ((o) ^ (((o) >> 3) & 0x70))

// ============================ small utility kernels ==========================
__device__ __forceinline__ uint32_t splitpack_h(float x) {
    __half h = __float2half_rn(x);
    float r = x - __half2float(h);
    __half l = __float2half_rn(r);
    return ((uint32_t)__half_as_ushort(l) << 16) | (uint32_t)__half_as_ushort(h);
}

__global__ __launch_bounds__(256) void split_kernel(const float4* __restrict__ src,
                                                    uint2* __restrict__ h, uint2* __restrict__ l) {
    int i = blockIdx.x * 256 + threadIdx.x;
    float4 v = src[i];
    uint32_t p0 = splitpack_h(v.x), p1 = splitpack_h(v.y), p2 = splitpack_h(v.z), p3 = splitpack_h(v.w);
    uint2 hh, ll;
    hh.x = (p0 & 0xFFFF) | (p1 << 16);  hh.y = (p2 & 0xFFFF) | (p3 << 16);
    ll.x = (p0 >> 16) | (p1 & 0xFFFF0000u);  ll.y = (p2 >> 16) | (p3 & 0xFFFF0000u);
    h[i] = hh; l[i] = ll;
}

__global__ __launch_bounds__(256) void half_kernel(const float4* __restrict__ src,
                                                   uint2* __restrict__ h) {
    int i = blockIdx.x * 256 + threadIdx.x;
    float4 v = src[i];
    uint2 hh;
    hh.x = (uint32_t)__half_as_ushort(__float2half_rn(v.x)) |
           ((uint32_t)__half_as_ushort(__float2half_rn(v.y)) << 16);
    hh.y = (uint32_t)__half_as_ushort(__float2half_rn(v.z)) |
           ((uint32_t)__half_as_ushort(__float2half_rn(v.w)) << 16);
    h[i] = hh;
}

__global__ __launch_bounds__(256) void wt_half_kernel(const float* __restrict__ W,
                                                      __half* __restrict__ th) {
    int i = blockIdx.x * 256 + threadIdx.x;           // Wt[h][d] = W[d][h]
    int hh = i >> 9, d = i & 511;
    th[i] = __float2half_rn(W[d * 512 + hh]);
}

__global__ __launch_bounds__(256) void dagt_kernel(const float* __restrict__ dag,
                                                   float* __restrict__ dagT) {
    int i = blockIdx.x * 256 + threadIdx.x;           // dagT[t][s] = dag[s][t]
    int t = i >> 10, s = i & 1023;
    dagT[i] = dag[s * 1024 + t];
}

__global__ __launch_bounds__(256) void softmax_kernel(const float* __restrict__ S,
                                                      uint2* __restrict__ Ph) {
    const long long row = blockIdx.x;
    const float* p = S + row * 1024;
    const int tid = threadIdx.x;
    float4 v = ((const float4*)p)[tid];

    __shared__ float red[256];
    float m = fmaxf(fmaxf(v.x, v.y), fmaxf(v.z, v.w));
    red[tid] = m; __syncthreads();
#pragma unroll
    for (int s = 128; s > 0; s >>= 1) { if (tid < s) red[tid] = fmaxf(red[tid], red[tid + s]); __syncthreads(); }
    const float mx = red[0]; __syncthreads();

    float4 e;
    e.x = __expf(v.x - mx); e.y = __expf(v.y - mx); e.z = __expf(v.z - mx); e.w = __expf(v.w - mx);
    red[tid] = e.x + e.y + e.z + e.w; __syncthreads();
#pragma unroll
    for (int s = 128; s > 0; s >>= 1) { if (tid < s) red[tid] += red[tid + s]; __syncthreads(); }
    const float inv = 1.0f / red[0];

    if (mx < -1e29f) { e.x = e.y = e.z = e.w = 0.0f; }
    else { e.x *= inv; e.y *= inv; e.z *= inv; e.w *= inv; }

    uint2 hh;
    hh.x = (uint32_t)__half_as_ushort(__float2half_rn(e.x)) |
           ((uint32_t)__half_as_ushort(__float2half_rn(e.y)) << 16);
    hh.y = (uint32_t)__half_as_ushort(__float2half_rn(e.z)) |
           ((uint32_t)__half_as_ushort(__float2half_rn(e.w)) << 16);
    Ph[row * 256 + tid] = hh;
}

// ============================ HMMA fp16 GEMM =================================
// C[256x128 CTA] = A[M,K] x B[N,K]^T. NPASS=2: A = Ah + Al (hi/lo fp16, 2 MMA
// passes). NPASS=1: A = Ah only. 8 warps 4(M)x2(N), warp tile 64x64, BK=64.
// NPASS==2: 2-stage pipeline (80KB/stage); NPASS==1: 3-stage (48KB/stage).
// EPI: 0 hi/lo fp16 (+bias) row-major (Q); 4 single fp16 (+bias) row-major (K);
//      3 single fp16 (+bias) transposed [h][t] (V^T); 1 fp32 masked logits; 2 fp32 out.
template <int NPASS>
struct GemmCfg {
    static constexpr int STAGE = (NPASS == 2) ? 81920 : 49152;
    static constexpr int NS    = (NPASS == 2) ? 2 : 3;
    static constexpr int SMEM  = STAGE * NS;
    static constexpr int BOFF  = (NPASS == 2) ? 65536 : 32768;
};

template <int NPASS, int EPI>
__global__ __launch_bounds__(256, 1) void gemm_hmma(
    const __half* __restrict__ Ah, const __half* __restrict__ Al,
    long long sA, int lda,
    const __half* __restrict__ B, long long sB, int ldb,
    int Kdim,
    float* __restrict__ Cf, long long sCf,
    __half* __restrict__ Ch, __half* __restrict__ Cl,
    const float* __restrict__ bias, const float* __restrict__ dagT)
{
    extern __shared__ char smem[];
    using C = GemmCfg<NPASS>;
    const int b = blockIdx.z;
    Ah += (long long)b * sA;
    if (NPASS == 2) Al += (long long)b * sA;
    B  += (long long)b * sB;

    const int mBase = blockIdx.y * 256;
    const int nBase = blockIdx.x * 128;
    const int tid = threadIdx.x, wid = tid >> 5, lane = tid & 31;
    const int warpM = (wid >> 1) * 64;
    const int warpN = (wid & 1) * 64;

    const uint32_t sb = smem_u32(smem);

    const __half* srcAh = Ah + (long long)mBase * lda;
    const __half* srcAl = (NPASS == 2) ? (Al + (long long)mBase * lda) : nullptr;
    const __half* srcB  = B  + (long long)nBase * ldb;

    auto load_stage = [&](int st, int k0) {
        const uint32_t stBase = sb + st * C::STAGE;
#pragma unroll
        for (int i = 0; i < 8; i++) {              // Ah: 256 rows x 8 chunks
            const int idx = (i << 8) | tid;
            const int row = idx >> 3, k8 = (idx & 7) << 3;
            CP_ASYNC16(stBase + SWZ128((uint32_t)(row * 128 + k8 * 2)),
                       srcAh + (long long)row * lda + k0 + k8);
        }
        if (NPASS == 2) {
#pragma unroll
            for (int i = 0; i < 8; i++) {          // Al
                const int idx = (i << 8) | tid;
                const int row = idx >> 3, k8 = (idx & 7) << 3;
                CP_ASYNC16(stBase + 32768 + SWZ128((uint32_t)(row * 128 + k8 * 2)),
                           srcAl + (long long)row * lda + k0 + k8);
            }
        }
#pragma unroll
        for (int i = 0; i < 4; i++) {              // B: 128 rows x 8 chunks
            const int idx = (i << 8) | tid;
            const int row = idx >> 3, k8 = (idx & 7) << 3;
            CP_ASYNC16(stBase + C::BOFF + SWZ128((uint32_t)(row * 128 + k8 * 2)),
                       srcB + (long long)row * ldb + k0 + k8);
        }
    };

    float acc[4][8][4];
#pragma unroll
    for (int mi = 0; mi < 4; mi++)
#pragma unroll
        for (int ni = 0; ni < 8; ni++)
#pragma unroll
            for (int c = 0; c < 4; c++) acc[mi][ni][c] = 0.0f;

    const int aRow  = warpM + (lane & 15);
    const int bRow  = warpN + (lane & 15);
    const int kHalf = (lane >> 4) * 8;

    const int nch = Kdim >> 6;
    load_stage(0, 0);
    CP_COMMIT();
    if (C::NS == 3 && nch > 1) { load_stage(1, 64); CP_COMMIT(); }

    for (int i = 0; i < nch; i++) {
        const int st = (C::NS == 2) ? (i & 1) : (i % 3);
        if (C::NS == 2) {
            if (i + 1 < nch) { load_stage((i + 1) & 1, (i + 1) << 6); CP_COMMIT(); CP_WAIT(1); }
            else CP_WAIT(0);
        } else {
            if (i + 2 < nch)      { load_stage((i + 2) % 3, (i + 2) << 6); CP_COMMIT(); CP_WAIT(2); }
            else if (i + 1 < nch) { CP_WAIT(1); }
            else                  { CP_WAIT(0); }
        }
        __syncthreads();

        const uint32_t ahB = sb + st * C::STAGE;
        const uint32_t alB = ahB + 32768;
        const uint32_t bB  = ahB + C::BOFF;

#pragma unroll
        for (int ks = 0; ks < 4; ks++) {
            const int kb = (ks * 16 + kHalf) * 2;
            uint32_t bf[8][2];
#pragma unroll
            for (int np = 0; np < 4; np++) {
                const uint32_t offB = SWZ128((uint32_t)((bRow + np * 16) * 128 + kb));
                uint32_t r0, r1, r2, r3;
                ldsm_x4(r0, r1, r2, r3, bB + offB);
                bf[np * 2 + 0][0] = r0; bf[np * 2 + 0][1] = r2;
                bf[np * 2 + 1][0] = r1; bf[np * 2 + 1][1] = r3;
            }
            uint32_t af[4][4];
#pragma unroll
            for (int mi = 0; mi < 4; mi++) {
                const uint32_t offA = SWZ128((uint32_t)((aRow + mi * 16) * 128 + kb));
                ldsm_x4(af[mi][0], af[mi][1], af[mi][2], af[mi][3], ahB + offA);
            }
#pragma unroll
            for (int mi = 0; mi < 4; mi++)
#pragma unroll
                for (int ni = 0; ni < 8; ni++)
                    mma_f16(acc[mi][ni], af[mi], bf[ni][0], bf[ni][1]);
            if (NPASS == 2) {
#pragma unroll
                for (int mi = 0; mi < 4; mi++) {
                    const uint32_t offA = SWZ128((uint32_t)((aRow + mi * 16) * 128 + kb));
                    ldsm_x4(af[mi][0], af[mi][1], af[mi][2], af[mi][3], alB + offA);
                }
#pragma unroll
                for (int mi = 0; mi < 4; mi++)
#pragma unroll
                    for (int ni = 0; ni < 8; ni++)
                        mma_f16(acc[mi][ni], af[mi], bf[ni][0], bf[ni][1]);
            }
        }
        __syncthreads();
    }

    // ---------------- epilogue: stage to smem, coalesced out -----------------
    uint32_t* stgU = (uint32_t*)smem;
    float*    stgF = (float*)smem;
    const int rBase = lane >> 2;
    const int cOff  = (lane & 3) * 2;

#pragma unroll
    for (int mi = 0; mi < 4; mi++) {
        const int r0 = warpM + mi * 16 + rBase;
        const int r1 = r0 + 8;
#pragma unroll
        for (int ni = 0; ni < 8; ni++) {
            const int col = warpN + ni * 8 + cOff;
            if (EPI == 0) {
                const float b0 = bias[nBase + col], b1 = bias[nBase + col + 1];
                stgU[r0 * 132 + col]     = splitpack_h(acc[mi][ni][0] + b0);
                stgU[r0 * 132 + col + 1] = splitpack_h(acc[mi][ni][1] + b1);
                stgU[r1 * 132 + col]     = splitpack_h(acc[mi][ni][2] + b0);
                stgU[r1 * 132 + col + 1] = splitpack_h(acc[mi][ni][3] + b1);
            } else if (EPI == 4) {
                const float b0 = bias[nBase + col], b1 = bias[nBase + col + 1];
                stgU[r0 * 132 + col]     = (uint32_t)__half_as_ushort(__float2half_rn(acc[mi][ni][0] + b0));
                stgU[r0 * 132 + col + 1] = (uint32_t)__half_as_ushort(__float2half_rn(acc[mi][ni][1] + b1));
                stgU[r1 * 132 + col]     = (uint32_t)__half_as_ushort(__float2half_rn(acc[mi][ni][2] + b0));
                stgU[r1 * 132 + col + 1] = (uint32_t)__half_as_ushort(__float2half_rn(acc[mi][ni][3] + b1));
            } else if (EPI == 3) {
                const float b0 = bias[nBase + col], b1 = bias[nBase + col + 1];
                stgU[col * 260 + r0]       = (uint32_t)__half_as_ushort(__float2half_rn(acc[mi][ni][0] + b0));
                stgU[(col + 1) * 260 + r0] = (uint32_t)__half_as_ushort(__float2half_rn(acc[mi][ni][1] + b1));
                stgU[col * 260 + r1]       = (uint32_t)__half_as_ushort(__float2half_rn(acc[mi][ni][2] + b0));
                stgU[(col + 1) * 260 + r1] = (uint32_t)__half_as_ushort(__float2half_rn(acc[mi][ni][3] + b1));
            } else {
                stgF[r0 * 132 + col] = acc[mi][ni][0]; stgF[r0 * 132 + col + 1] = acc[mi][ni][1];
                stgF[r1 * 132 + col] = acc[mi][ni][2]; stgF[r1 * 132 + col + 1] = acc[mi][ni][3];
            }
        }
    }
    __syncthreads();

    if (EPI == 0) {               // row-major hi/lo fp16
#pragma unroll
        for (int i = 0; i < 32; i++) {
            const int q = tid + i * 256;
            const int row = q >> 5, c4 = (q & 31) << 2;
            uint32_t w0 = stgU[row * 132 + c4], w1 = stgU[row * 132 + c4 + 1];
            uint32_t w2 = stgU[row * 132 + c4 + 2], w3 = stgU[row * 132 + c4 + 3];
            uint2 hh, ll;
            hh.x = (w0 & 0xFFFF) | (w1 << 16);  hh.y = (w2 & 0xFFFF) | (w3 << 16);
            ll.x = (w0 >> 16) | (w1 & 0xFFFF0000u);  ll.y = (w2 >> 16) | (w3 & 0xFFFF0000u);
            const long long gi = (long long)(mBase + row) * 512 + nBase + c4;
            *(uint2*)(Ch + gi) = hh;  *(uint2*)(Cl + gi) = ll;
        }
    } else if (EPI == 4) {        // row-major single fp16
#pragma unroll
        for (int i = 0; i < 32; i++) {
            const int q = tid + i * 256;
            const int row = q >> 5, c4 = (q & 31) << 2;
            uint32_t w0 = stgU[row * 132 + c4], w1 = stgU[row * 132 + c4 + 1];
            uint32_t w2 = stgU[row * 132 + c4 + 2], w3 = stgU[row * 132 + c4 + 3];
            uint2 hh;
            hh.x = (w0 & 0xFFFF) | (w1 << 16);  hh.y = (w2 & 0xFFFF) | (w3 << 16);
            const long long gi = (long long)(mBase + row) * 512 + nBase + c4;
            *(uint2*)(Ch + gi) = hh;
        }
    } else if (EPI == 3) {        // transposed single fp16: out[bat][h][t]
#pragma unroll
        for (int i = 0; i < 32; i++) {
            const int q = tid + i * 256;
            const int c = q >> 6, r4 = (q & 63) << 2;
            uint32_t w0 = stgU[c * 260 + r4], w1 = stgU[c * 260 + r4 + 1];
            uint32_t w2 = stgU[c * 260 + r4 + 2], w3 = stgU[c * 260 + r4 + 3];
            uint2 hh;
            hh.x = (w0 & 0xFFFF) | (w1 << 16);  hh.y = (w2 & 0xFFFF) | (w3 << 16);
            const int gt = mBase + r4;
            const int bat = gt >> 10, t0 = gt & 1023;
            const long long gi = ((long long)bat * 512 + (nBase + c)) * 1024 + t0;
            *(uint2*)(Ch + gi) = hh;
        }
    } else if (EPI == 1) {        // scores: scale + dag mask -> fp32 logits
        const float scale = 0.044194173824159216f;   // 1/sqrt(512)
#pragma unroll
        for (int i = 0; i < 32; i++) {
            const int q = tid + i * 256;
            const int row = q >> 5, c4 = (q & 31) << 2;
            const int t = mBase + row;
            float4 dg = *(const float4*)(dagT + (long long)t * 1024 + nBase + c4);
            float v0 = stgF[row * 132 + c4]     * scale * dg.x;
            float v1 = stgF[row * 132 + c4 + 1] * scale * dg.y;
            float v2 = stgF[row * 132 + c4 + 2] * scale * dg.z;
            float v3 = stgF[row * 132 + c4 + 3] * scale * dg.w;
            float4 o;
            o.x = (v0 == 0.0f) ? NEGV : v0;
            o.y = (v1 == 0.0f) ? NEGV : v1;
            o.z = (v2 == 0.0f) ? NEGV : v2;
            o.w = (v3 == 0.0f) ? NEGV : v3;
            *(float4*)(Cf + (long long)b * sCf + (long long)t * 1024 + nBase + c4) = o;
        }
    } else {                      // EPI 2: fp32 out, ldc = 512
#pragma unroll
        for (int i = 0; i < 32; i++) {
            const int q = tid + i * 256;
            const int row = q >> 5, c4 = (q & 31) << 2;
            float4 o;
            o.x = stgF[row * 132 + c4];
            o.y = stgF[row * 132 + c4 + 1];
            o.z = stgF[row * 132 + c4 + 2];
            o.w = stgF[row * 132 + c4 + 3];
            *(float4*)(Cf + (long long)b * sCf + (long long)(mBase + row) * 512 + nBase + c4) = o;
        }
    }
}

// ============================ launch =========================================
extern "C" void kernel_launch(void* const* d_in, const int* in_sizes, int n_in,
                              void* d_out, int out_size)
{
    const float* X   = (const float*)d_in[0];
    const float* Y   = (const float*)d_in[1];
    const float* dag = (const float*)d_in[2];
    const float* Wk  = (const float*)d_in[3];
    const float* bk  = (const float*)d_in[4];
    const float* Wq  = (const float*)d_in[5];
    const float* bq  = (const float*)d_in[6];
    const float* Wv  = (const float*)d_in[7];
    const float* bv  = (const float*)d_in[8];
    float* O = (float*)d_out;

    __half *Xh, *Yh, *Yl, *Kh, *Qh, *Ql, *Vth, *Wth, *Ph;
    float *S, *dagT;
    cudaGetSymbolAddress((void**)&Xh, g_Xh);
    cudaGetSymbolAddress((void**)&Yh, g_Yh);   cudaGetSymbolAddress((void**)&Yl, g_Yl);
    cudaGetSymbolAddress((void**)&Kh, g_Kh);
    cudaGetSymbolAddress((void**)&Qh, g_Qh);   cudaGetSymbolAddress((void**)&Ql, g_Ql);
    cudaGetSymbolAddress((void**)&Vth, g_Vth);
    cudaGetSymbolAddress((void**)&Wth, g_Wth);
    cudaGetSymbolAddress((void**)&Ph, g_Ph);
    cudaGetSymbolAddress((void**)&S, g_S);     cudaGetSymbolAddress((void**)&dagT, g_dagT);

    cudaFuncSetAttribute(gemm_hmma<1,4>, cudaFuncAttributeMaxDynamicSharedMemorySize, GemmCfg<1>::SMEM);
    cudaFuncSetAttribute(gemm_hmma<2,0>, cudaFuncAttributeMaxDynamicSharedMemorySize, GemmCfg<2>::SMEM);
    cudaFuncSetAttribute(gemm_hmma<1,3>, cudaFuncAttributeMaxDynamicSharedMemorySize, GemmCfg<1>::SMEM);
    cudaFuncSetAttribute(gemm_hmma<2,1>, cudaFuncAttributeMaxDynamicSharedMemorySize, GemmCfg<2>::SMEM);
    cudaFuncSetAttribute(gemm_hmma<1,2>, cudaFuncAttributeMaxDynamicSharedMemorySize, GemmCfg<1>::SMEM);

    // ---- prep ----
    half_kernel <<<32768, 256>>>((const float4*)X, (uint2*)Xh);
    split_kernel<<<32768, 256>>>((const float4*)Y, (uint2*)Yh, (uint2*)Yl);
    wt_half_kernel<<<1024, 256>>>(Wk, Wth);
    wt_half_kernel<<<1024, 256>>>(Wq, Wth + 262144);
    wt_half_kernel<<<1024, 256>>>(Wv, Wth + 524288);
    dagt_kernel<<<4096, 256>>>(dag, dagT);

    dim3 blk(256);

    // ---- projections: [65536,512] x Wt[512,512]^T ----
    dim3 gproj(4, 256, 1);
    gemm_hmma<1,4><<<gproj, blk, GemmCfg<1>::SMEM>>>(Xh, nullptr, 0, 512, Wth,          0, 512, 512,
                                                     nullptr, 0, Kh, nullptr, bk, nullptr);
    gemm_hmma<2,0><<<gproj, blk, GemmCfg<2>::SMEM>>>(Yh, Yl,      0, 512, Wth + 262144, 0, 512, 512,
                                                     nullptr, 0, Qh, Ql, bq, nullptr);
    gemm_hmma<1,3><<<gproj, blk, GemmCfg<1>::SMEM>>>(Xh, nullptr, 0, 512, Wth + 524288, 0, 512, 512,
                                                     nullptr, 0, Vth, nullptr, bv, nullptr);

    // ---- scores: per-batch Q[1024,512] x K[1024,512]^T -> masked logits -----
    dim3 gsc(8, 4, 64);
    gemm_hmma<2,1><<<gsc, blk, GemmCfg<2>::SMEM>>>(Qh, Ql, 524288, 512, Kh, 524288, 512, 512,
                                                   S, 1048576, nullptr, nullptr, nullptr, dagT);

    // ---- softmax -> probs single fp16 ----
    softmax_kernel<<<65536, 256>>>(S, (uint2*)Ph);

    // ---- output: per-batch P[1024,1024] x Vt[512,1024]^T -> fp32 out --------
    dim3 gav(4, 4, 64);
    gemm_hmma<1,2><<<gav, blk, GemmCfg<1>::SMEM>>>(Ph, nullptr, 1048576, 1024, Vth, 524288, 1024, 1024,
                                                   O, 524288, nullptr, nullptr, nullptr, nullptr);
}

// round 7
// speedup vs baseline: 5.4857x; 1.2810x over previous
#include <cuda_runtime.h>
#include <cuda_fp16.h>
#include <cstdint>

#define NEGV (-1e30f)

// ============================ scratch (no allocs) ============================
__device__ __half g_Xh[33554432];                       // X fp16
__device__ __half g_Yh[33554432];                       // Y fp16
__device__ __half g_Kh[33554432];                       // K fp16 [b][t][h]
__device__ __half g_Qh[33554432];                       // Q fp16 [b][t][h]
__device__ __half g_Vth[33554432];                      // V^T fp16 [b][h][t]
__device__ float  g_S [67108864];                       // logits [b][t][s]
__device__ __half g_Ph[67108864];                       // probs fp16
__device__ __half g_Wth[786432];                        // 3x W^T [h][d] fp16
__device__ float  g_dagT[1048576];                      // dag transposed [t][s]

// ============================ PTX helpers (base sm_103 ISA) ==================
__device__ __forceinline__ uint32_t smem_u32(const void* p) {
    uint32_t a;
    asm("{ .reg .u64 t; cvta.to.shared.u64 t, %1; cvt.u32.u64 %0, t; }" : "=r"(a) : "l"(p));
    return a;
}
#define CP_ASYNC16(dst, src) \
    asm volatile("cp.async.cg.shared.global [%0], [%1], 16;" :: "r"(dst), "l"(src))
#define CP_COMMIT() asm volatile("cp.async.commit_group;" ::: "memory")
#define CP_WAIT(n)  asm volatile("cp.async.wait_group %0;" :: "n"(n) : "memory")

__device__ __forceinline__ void ldsm_x4(uint32_t& r0, uint32_t& r1, uint32_t& r2, uint32_t& r3,
                                        uint32_t addr) {
    asm volatile("ldmatrix.sync.aligned.m8n8.x4.shared.b16 {%0,%1,%2,%3}, [%4];"
                 : "=r"(r0), "=r"(r1), "=r"(r2), "=r"(r3) : "r"(addr));
}
__device__ __forceinline__ void mma_f16(float* c, const uint32_t* a, uint32_t b0, uint32_t b1) {
    asm volatile(
        "mma.sync.aligned.m16n8k16.row.col.f32.f16.f16.f32 "
        "{%0,%1,%2,%3}, {%4,%5,%6,%7}, {%8,%9}, {%0,%1,%2,%3};"
        : "+f"(c[0]), "+f"(c[1]), "+f"(c[2]), "+f"(c[3])
        : "r"(a[0]), "r"(a[1]), "r"(a[2]), "r"(a[3]), "r"(b0), "r"(b1));
}
#define SWZ128(o) ((o) ^ (((o) >> 3) & 0x70))

// ============================ small utility kernels ==========================
__global__ __launch_bounds__(256) void half_kernel(const float4* __restrict__ src,
                                                   uint2* __restrict__ h) {
    int i = blockIdx.x * 256 + threadIdx.x;
    float4 v = src[i];
    uint2 hh;
    hh.x = (uint32_t)__half_as_ushort(__float2half_rn(v.x)) |
           ((uint32_t)__half_as_ushort(__float2half_rn(v.y)) << 16);
    hh.y = (uint32_t)__half_as_ushort(__float2half_rn(v.z)) |
           ((uint32_t)__half_as_ushort(__float2half_rn(v.w)) << 16);
    h[i] = hh;
}

__global__ __launch_bounds__(256) void wt_half_kernel(const float* __restrict__ W,
                                                      __half* __restrict__ th) {
    int i = blockIdx.x * 256 + threadIdx.x;           // Wt[h][d] = W[d][h]
    int hh = i >> 9, d = i & 511;
    th[i] = __float2half_rn(W[d * 512 + hh]);
}

__global__ __launch_bounds__(256) void dagt_kernel(const float* __restrict__ dag,
                                                   float* __restrict__ dagT) {
    int i = blockIdx.x * 256 + threadIdx.x;           // dagT[t][s] = dag[s][t]
    int t = i >> 10, s = i & 1023;
    dagT[i] = dag[s * 1024 + t];
}

__global__ __launch_bounds__(256) void softmax_kernel(const float* __restrict__ S,
                                                      uint2* __restrict__ Ph) {
    const long long row = blockIdx.x;
    const float* p = S + row * 1024;
    const int tid = threadIdx.x;
    float4 v = ((const float4*)p)[tid];

    __shared__ float red[256];
    float m = fmaxf(fmaxf(v.x, v.y), fmaxf(v.z, v.w));
    red[tid] = m; __syncthreads();
#pragma unroll
    for (int s = 128; s > 0; s >>= 1) { if (tid < s) red[tid] = fmaxf(red[tid], red[tid + s]); __syncthreads(); }
    const float mx = red[0]; __syncthreads();

    float4 e;
    e.x = __expf(v.x - mx); e.y = __expf(v.y - mx); e.z = __expf(v.z - mx); e.w = __expf(v.w - mx);
    red[tid] = e.x + e.y + e.z + e.w; __syncthreads();
#pragma unroll
    for (int s = 128; s > 0; s >>= 1) { if (tid < s) red[tid] += red[tid + s]; __syncthreads(); }
    const float inv = 1.0f / red[0];

    if (mx < -1e29f) { e.x = e.y = e.z = e.w = 0.0f; }
    else { e.x *= inv; e.y *= inv; e.z *= inv; e.w *= inv; }

    uint2 hh;
    hh.x = (uint32_t)__half_as_ushort(__float2half_rn(e.x)) |
           ((uint32_t)__half_as_ushort(__float2half_rn(e.y)) << 16);
    hh.y = (uint32_t)__half_as_ushort(__float2half_rn(e.z)) |
           ((uint32_t)__half_as_ushort(__float2half_rn(e.w)) << 16);
    Ph[row * 256 + tid] = hh;
}

// ============================ HMMA fp16 GEMM (1-pass) ========================
// C[256x128 CTA] = A[M,K] x B[N,K]^T, fp32 accum. 8 warps 4(M)x2(N),
// warp tile 64x64, BK=64, 3-stage cp.async pipeline (48KB/stage).
// EPI: 4 fp16 (+bias) row-major; 3 fp16 (+bias) transposed [h][t];
//      1 fp32 masked logits (scale+dag); 2 fp32 out.
static constexpr int STAGE_BYTES = 49152;
static constexpr int SMEM_BYTES  = 3 * STAGE_BYTES;   // 144KB

template <int EPI>
__global__ __launch_bounds__(256, 1) void gemm_hmma(
    const __half* __restrict__ A, long long sA, int lda,
    const __half* __restrict__ B, long long sB, int ldb,
    int Kdim,
    float* __restrict__ Cf, long long sCf,
    __half* __restrict__ Ch,
    const float* __restrict__ bias, const float* __restrict__ dagT)
{
    extern __shared__ char smem[];
    const int b = blockIdx.z;
    A += (long long)b * sA;
    B += (long long)b * sB;

    const int mBase = blockIdx.y * 256;
    const int nBase = blockIdx.x * 128;
    const int tid = threadIdx.x, wid = tid >> 5, lane = tid & 31;
    const int warpM = (wid >> 1) * 64;
    const int warpN = (wid & 1) * 64;

    const uint32_t sb = smem_u32(smem);

    const __half* srcA = A + (long long)mBase * lda;
    const __half* srcB = B + (long long)nBase * ldb;

    auto load_stage = [&](int st, int k0) {
        const uint32_t stBase = sb + st * STAGE_BYTES;
#pragma unroll
        for (int i = 0; i < 8; i++) {              // A: 256 rows x 8 chunks of 8
            const int idx = (i << 8) | tid;
            const int row = idx >> 3, k8 = (idx & 7) << 3;
            CP_ASYNC16(stBase + SWZ128((uint32_t)(row * 128 + k8 * 2)),
                       srcA + (long long)row * lda + k0 + k8);
        }
#pragma unroll
        for (int i = 0; i < 4; i++) {              // B: 128 rows x 8 chunks
            const int idx = (i << 8) | tid;
            const int row = idx >> 3, k8 = (idx & 7) << 3;
            CP_ASYNC16(stBase + 32768 + SWZ128((uint32_t)(row * 128 + k8 * 2)),
                       srcB + (long long)row * ldb + k0 + k8);
        }
    };

    float acc[4][8][4];
#pragma unroll
    for (int mi = 0; mi < 4; mi++)
#pragma unroll
        for (int ni = 0; ni < 8; ni++)
#pragma unroll
            for (int c = 0; c < 4; c++) acc[mi][ni][c] = 0.0f;

    const int aRow  = warpM + (lane & 15);
    const int bRow  = warpN + (lane & 15);
    const int kHalf = (lane >> 4) * 8;

    const int nch = Kdim >> 6;
    load_stage(0, 0);
    CP_COMMIT();
    if (nch > 1) { load_stage(1, 64); CP_COMMIT(); }

    for (int i = 0; i < nch; i++) {
        const int st = i % 3;
        if (i + 2 < nch)      { load_stage((i + 2) % 3, (i + 2) << 6); CP_COMMIT(); CP_WAIT(2); }
        else if (i + 1 < nch) { CP_WAIT(1); }
        else                  { CP_WAIT(0); }
        __syncthreads();

        const uint32_t aB = sb + st * STAGE_BYTES;
        const uint32_t bB = aB + 32768;

#pragma unroll
        for (int ks = 0; ks < 4; ks++) {
            const int kb = (ks * 16 + kHalf) * 2;
            uint32_t bf[8][2];
#pragma unroll
            for (int np = 0; np < 4; np++) {
                const uint32_t offB = SWZ128((uint32_t)((bRow + np * 16) * 128 + kb));
                uint32_t r0, r1, r2, r3;
                ldsm_x4(r0, r1, r2, r3, bB + offB);
                bf[np * 2 + 0][0] = r0; bf[np * 2 + 0][1] = r2;
                bf[np * 2 + 1][0] = r1; bf[np * 2 + 1][1] = r3;
            }
            uint32_t af[4][4];
#pragma unroll
            for (int mi = 0; mi < 4; mi++) {
                const uint32_t offA = SWZ128((uint32_t)((aRow + mi * 16) * 128 + kb));
                ldsm_x4(af[mi][0], af[mi][1], af[mi][2], af[mi][3], aB + offA);
            }
#pragma unroll
            for (int mi = 0; mi < 4; mi++)
#pragma unroll
                for (int ni = 0; ni < 8; ni++)
                    mma_f16(acc[mi][ni], af[mi], bf[ni][0], bf[ni][1]);
        }
        __syncthreads();
    }

    // ---------------- epilogue: stage to smem, coalesced out -----------------
    uint32_t* stgU = (uint32_t*)smem;
    float*    stgF = (float*)smem;
    const int rBase = lane >> 2;
    const int cOff  = (lane & 3) * 2;

#pragma unroll
    for (int mi = 0; mi < 4; mi++) {
        const int r0 = warpM + mi * 16 + rBase;
        const int r1 = r0 + 8;
#pragma unroll
        for (int ni = 0; ni < 8; ni++) {
            const int col = warpN + ni * 8 + cOff;
            if (EPI == 4) {
                const float b0 = bias[nBase + col], b1 = bias[nBase + col + 1];
                stgU[r0 * 132 + col]     = (uint32_t)__half_as_ushort(__float2half_rn(acc[mi][ni][0] + b0));
                stgU[r0 * 132 + col + 1] = (uint32_t)__half_as_ushort(__float2half_rn(acc[mi][ni][1] + b1));
                stgU[r1 * 132 + col]     = (uint32_t)__half_as_ushort(__float2half_rn(acc[mi][ni][2] + b0));
                stgU[r1 * 132 + col + 1] = (uint32_t)__half_as_ushort(__float2half_rn(acc[mi][ni][3] + b1));
            } else if (EPI == 3) {
                const float b0 = bias[nBase + col], b1 = bias[nBase + col + 1];
                stgU[col * 260 + r0]       = (uint32_t)__half_as_ushort(__float2half_rn(acc[mi][ni][0] + b0));
                stgU[(col + 1) * 260 + r0] = (uint32_t)__half_as_ushort(__float2half_rn(acc[mi][ni][1] + b1));
                stgU[col * 260 + r1]       = (uint32_t)__half_as_ushort(__float2half_rn(acc[mi][ni][2] + b0));
                stgU[(col + 1) * 260 + r1] = (uint32_t)__half_as_ushort(__float2half_rn(acc[mi][ni][3] + b1));
            } else {
                stgF[r0 * 132 + col] = acc[mi][ni][0]; stgF[r0 * 132 + col + 1] = acc[mi][ni][1];
                stgF[r1 * 132 + col] = acc[mi][ni][2]; stgF[r1 * 132 + col + 1] = acc[mi][ni][3];
            }
        }
    }
    __syncthreads();

    if (EPI == 4) {               // row-major fp16
#pragma unroll
        for (int i = 0; i < 32; i++) {
            const int q = tid + i * 256;
            const int row = q >> 5, c4 = (q & 31) << 2;
            uint32_t w0 = stgU[row * 132 + c4], w1 = stgU[row * 132 + c4 + 1];
            uint32_t w2 = stgU[row * 132 + c4 + 2], w3 = stgU[row * 132 + c4 + 3];
            uint2 hh;
            hh.x = (w0 & 0xFFFF) | (w1 << 16);  hh.y = (w2 & 0xFFFF) | (w3 << 16);
            const long long gi = (long long)(mBase + row) * 512 + nBase + c4;
            *(uint2*)(Ch + gi) = hh;
        }
    } else if (EPI == 3) {        // transposed fp16: out[bat][h][t]
#pragma unroll
        for (int i = 0; i < 32; i++) {
            const int q = tid + i * 256;
            const int c = q >> 6, r4 = (q & 63) << 2;
            uint32_t w0 = stgU[c * 260 + r4], w1 = stgU[c * 260 + r4 + 1];
            uint32_t w2 = stgU[c * 260 + r4 + 2], w3 = stgU[c * 260 + r4 + 3];
            uint2 hh;
            hh.x = (w0 & 0xFFFF) | (w1 << 16);  hh.y = (w2 & 0xFFFF) | (w3 << 16);
            const int gt = mBase + r4;
            const int bat = gt >> 10, t0 = gt & 1023;
            const long long gi = ((long long)bat * 512 + (nBase + c)) * 1024 + t0;
            *(uint2*)(Ch + gi) = hh;
        }
    } else if (EPI == 1) {        // scores: scale + dag mask -> fp32 logits
        const float scale = 0.044194173824159216f;   // 1/sqrt(512)
#pragma unroll
        for (int i = 0; i < 32; i++) {
            const int q = tid + i * 256;
            const int row = q >> 5, c4 = (q & 31) << 2;
            const int t = mBase + row;
            float4 dg = *(const float4*)(dagT + (long long)t * 1024 + nBase + c4);
            float v0 = stgF[row * 132 + c4]     * scale * dg.x;
            float v1 = stgF[row * 132 + c4 + 1] * scale * dg.y;
            float v2 = stgF[row * 132 + c4 + 2] * scale * dg.z;
            float v3 = stgF[row * 132 + c4 + 3] * scale * dg.w;
            float4 o;
            o.x = (v0 == 0.0f) ? NEGV : v0;
            o.y = (v1 == 0.0f) ? NEGV : v1;
            o.z = (v2 == 0.0f) ? NEGV : v2;
            o.w = (v3 == 0.0f) ? NEGV : v3;
            *(float4*)(Cf + (long long)b * sCf + (long long)t * 1024 + nBase + c4) = o;
        }
    } else {                      // EPI 2: fp32 out, ldc = 512
#pragma unroll
        for (int i = 0; i < 32; i++) {
            const int q = tid + i * 256;
            const int row = q >> 5, c4 = (q & 31) << 2;
            float4 o;
            o.x = stgF[row * 132 + c4];
            o.y = stgF[row * 132 + c4 + 1];
            o.z = stgF[row * 132 + c4 + 2];
            o.w = stgF[row * 132 + c4 + 3];
            *(float4*)(Cf + (long long)b * sCf + (long long)(mBase + row) * 512 + nBase + c4) = o;
        }
    }
}

// ============================ launch =========================================
extern "C" void kernel_launch(void* const* d_in, const int* in_sizes, int n_in,
                              void* d_out, int out_size)
{
    const float* X   = (const float*)d_in[0];
    const float* Y   = (const float*)d_in[1];
    const float* dag = (const float*)d_in[2];
    const float* Wk  = (const float*)d_in[3];
    const float* bk  = (const float*)d_in[4];
    const float* Wq  = (const float*)d_in[5];
    const float* bq  = (const float*)d_in[6];
    const float* Wv  = (const float*)d_in[7];
    const float* bv  = (const float*)d_in[8];
    float* O = (float*)d_out;

    __half *Xh, *Yh, *Kh, *Qh, *Vth, *Wth, *Ph;
    float *S, *dagT;
    cudaGetSymbolAddress((void**)&Xh, g_Xh);
    cudaGetSymbolAddress((void**)&Yh, g_Yh);
    cudaGetSymbolAddress((void**)&Kh, g_Kh);
    cudaGetSymbolAddress((void**)&Qh, g_Qh);
    cudaGetSymbolAddress((void**)&Vth, g_Vth);
    cudaGetSymbolAddress((void**)&Wth, g_Wth);
    cudaGetSymbolAddress((void**)&Ph, g_Ph);
    cudaGetSymbolAddress((void**)&S, g_S);
    cudaGetSymbolAddress((void**)&dagT, g_dagT);

    cudaFuncSetAttribute(gemm_hmma<4>, cudaFuncAttributeMaxDynamicSharedMemorySize, SMEM_BYTES);
    cudaFuncSetAttribute(gemm_hmma<3>, cudaFuncAttributeMaxDynamicSharedMemorySize, SMEM_BYTES);
    cudaFuncSetAttribute(gemm_hmma<1>, cudaFuncAttributeMaxDynamicSharedMemorySize, SMEM_BYTES);
    cudaFuncSetAttribute(gemm_hmma<2>, cudaFuncAttributeMaxDynamicSharedMemorySize, SMEM_BYTES);

    // ---- prep ----
    half_kernel<<<32768, 256>>>((const float4*)X, (uint2*)Xh);
    half_kernel<<<32768, 256>>>((const float4*)Y, (uint2*)Yh);
    wt_half_kernel<<<1024, 256>>>(Wk, Wth);
    wt_half_kernel<<<1024, 256>>>(Wq, Wth + 262144);
    wt_half_kernel<<<1024, 256>>>(Wv, Wth + 524288);
    dagt_kernel<<<4096, 256>>>(dag, dagT);

    dim3 blk(256);

    // ---- projections: [65536,512] x Wt[512,512]^T ----
    dim3 gproj(4, 256, 1);
    gemm_hmma<4><<<gproj, blk, SMEM_BYTES>>>(Xh, 0, 512, Wth,          0, 512, 512,
                                             nullptr, 0, Kh, bk, nullptr);
    gemm_hmma<4><<<gproj, blk, SMEM_BYTES>>>(Yh, 0, 512, Wth + 262144, 0, 512, 512,
                                             nullptr, 0, Qh, bq, nullptr);
    gemm_hmma<3><<<gproj, blk, SMEM_BYTES>>>(Xh, 0, 512, Wth + 524288, 0, 512, 512,
                                             nullptr, 0, Vth, bv, nullptr);

    // ---- scores: per-batch Q[1024,512] x K[1024,512]^T -> masked logits -----
    dim3 gsc(8, 4, 64);
    gemm_hmma<1><<<gsc, blk, SMEM_BYTES>>>(Qh, 524288, 512, Kh, 524288, 512, 512,
                                           S, 1048576, nullptr, nullptr, dagT);

    // ---- softmax -> probs fp16 ----
    softmax_kernel<<<65536, 256>>>(S, (uint2*)Ph);

    // ---- output: per-batch P[1024,1024] x Vt[512,1024]^T -> fp32 out --------
    dim3 gav(4, 4, 64);
    gemm_hmma<2><<<gav, blk, SMEM_BYTES>>>(Ph, 1048576, 1024, Vth, 524288, 1024, 1024,
                                           O, 524288, nullptr, nullptr, nullptr);
}